// round 6
// baseline (speedup 1.0000x reference)
#include <cuda_runtime.h>
#include <cuda_bf16.h>
#include <math.h>
#include <stdint.h>

// ---------------- problem constants ----------------
#define BATCH   32
#define CHN     384
#define HH      28
#define WW      28
#define NTOK    784
#define HEADS   12
#define HDIM    32
#define HIDDEN  1536
#define MROWS   (BATCH*NTOK)       // 25088
#define SCALE_K 0.17677669529663687f

// ---------------- scratch ----------------
__device__ float g_nchwA[BATCH*CHN*NTOK];
__device__ float g_xt[MROWS*CHN];
__device__ float g_qkv[(size_t)MROWS*3*CHN];
__device__ float g_attn[BATCH*HEADS*HDIM*HDIM];
__device__ float g_x2[MROWS*CHN];
__device__ float g_x3[MROWS*CHN];
__device__ float g_y[MROWS*CHN];
// dedup split activations [rows, 2K]  layout [hi|lo]
__device__ __align__(16) __nv_bfloat16 g_curS[(size_t)MROWS*2*CHN];
__device__ __align__(16) __nv_bfloat16 g_aoS[(size_t)MROWS*2*CHN];
__device__ __align__(16) __nv_bfloat16 g_hidS[(size_t)MROWS*2*HIDDEN];
// dedup split weights [N, 2K]  layout [hi|lo]
__device__ __align__(16) __nv_bfloat16 g_wqkvS[(size_t)(3*CHN)*2*CHN];
__device__ __align__(16) __nv_bfloat16 g_wprojS[(size_t)CHN*2*CHN];
__device__ __align__(16) __nv_bfloat16 g_wfc1S[(size_t)HIDDEN*2*CHN];
__device__ __align__(16) __nv_bfloat16 g_wfc2S[(size_t)CHN*2*HIDDEN];

// ---------------- helpers ----------------
__device__ __forceinline__ uint32_t smem_u32(const void* p) {
    uint32_t a;
    asm("{ .reg .u64 t; cvta.to.shared.u64 t, %1; cvt.u32.u64 %0, t; }" : "=r"(a) : "l"(p));
    return a;
}
#define CP16(dst, src) \
    asm volatile("cp.async.cg.shared.global [%0], [%1], 16;" :: "r"(dst), "l"(src))
#define CP_COMMIT() asm volatile("cp.async.commit_group;" ::: "memory")
#define CP_WAIT1()  asm volatile("cp.async.wait_group 1;" ::: "memory")

#define LDMX4(r0,r1,r2,r3,addr) \
    asm volatile("ldmatrix.sync.aligned.m8n8.x4.shared.b16 {%0,%1,%2,%3}, [%4];" \
                 : "=r"(r0), "=r"(r1), "=r"(r2), "=r"(r3) : "r"(addr))

#define MMA16816(d, a, b) \
    asm volatile("mma.sync.aligned.m16n8k16.row.col.f32.bf16.bf16.f32 " \
        "{%0,%1,%2,%3}, {%4,%5,%6,%7}, {%8,%9}, {%0,%1,%2,%3};" \
        : "+f"((d)[0]), "+f"((d)[1]), "+f"((d)[2]), "+f"((d)[3]) \
        : "r"((a)[0]), "r"((a)[1]), "r"((a)[2]), "r"((a)[3]), "r"((b)[0]), "r"((b)[1]))

// ---------------- mma.sync bf16 GEMM, fused 3-phase split ----------------
// Stage (32KB): Ah @0, Al @8KB, Bh @16KB, Bl @24KB.  Each subtile 128 rows x 32 bf16,
// row = 64B, swizzle chunk c' = c ^ ((row>>1)&3).  3-stage cp.async ring.
// Per base-K chunk: acc += Ah*Bh + Ah*Bl + Al*Bh  (all fp32 accum).
#define STG_SZ    32768
#define GEMM_SMEM (3*STG_SZ)

__device__ __forceinline__ void issue_chunk(
    uint32_t sb, int st, const char* Ab, const char* Bb,
    int m0, int n0, int twoKb, int Kb, int kk, int tid)
{
    uint32_t sA = sb + st * STG_SZ;
    int r = tid >> 2, c = tid & 3;
    uint32_t soff = (r << 6) + ((c ^ ((r >> 1) & 3)) << 4);
    {   // A rows (hi + lo)
        const char* gh = Ab + (((size_t)(m0 + r) * twoKb + kk + (c << 3)) << 1);
        CP16(sA + soff, gh);                       // Ah (rows 0-63)
        CP16(sA + 8192 + soff, gh + 2*Kb);         // Al
        const char* gh2 = Ab + (((size_t)(m0 + 64 + r) * twoKb + kk + (c << 3)) << 1);
        uint32_t r2 = r + 64;
        uint32_t soff2 = (r2 << 6) + ((c ^ ((r2 >> 1) & 3)) << 4);
        CP16(sA + soff2, gh2);                     // Ah (rows 64-127)
        CP16(sA + 8192 + soff2, gh2 + 2*Kb);       // Al
    }
    {   // B rows (hi + lo)
        const char* gh = Bb + (((size_t)(n0 + r) * twoKb + kk + (c << 3)) << 1);
        CP16(sA + 16384 + soff, gh);               // Bh
        CP16(sA + 24576 + soff, gh + 2*Kb);        // Bl
        const char* gh2 = Bb + (((size_t)(n0 + 64 + r) * twoKb + kk + (c << 3)) << 1);
        uint32_t r2 = r + 64;
        uint32_t soff2 = (r2 << 6) + ((c ^ ((r2 >> 1) & 3)) << 4);
        CP16(sA + 16384 + soff2, gh2);             // Bh
        CP16(sA + 24576 + soff2, gh2 + 2*Kb);      // Bl
    }
}

__global__ void __launch_bounds__(256, 2) gemm_mma(
    const __nv_bfloat16* __restrict__ A, const __nv_bfloat16* __restrict__ Bw,
    const float* __restrict__ bias, const float* __restrict__ res,
    float* __restrict__ outF, __nv_bfloat16* __restrict__ outS,
    int Ntot, int Kb, int act)
{
    extern __shared__ __align__(128) char smem[];
    uint32_t sb = smem_u32(smem);
    int tid = threadIdx.x, lane = tid & 31, w = tid >> 5;
    int wm0 = (w & 1) * 64;
    int wn0 = (w >> 1) * 32;
    int m0 = blockIdx.y * 128, n0 = blockIdx.x * 128;

    const char* Ab = (const char*)A;
    const char* Bb = (const char*)Bw;
    int nch = Kb >> 5;
    int twoKb = 2 * Kb;

    float acc[4][4][4];
    #pragma unroll
    for (int i = 0; i < 4; i++)
        #pragma unroll
        for (int j = 0; j < 4; j++)
            #pragma unroll
            for (int q = 0; q < 4; q++) acc[i][j][q] = 0.f;

    issue_chunk(sb, 0, Ab, Bb, m0, n0, twoKb, Kb, 0,  tid); CP_COMMIT();
    issue_chunk(sb, 1, Ab, Bb, m0, n0, twoKb, Kb, 32, tid); CP_COMMIT();

    for (int ch = 0; ch < nch; ch++) {
        CP_WAIT1();
        __syncthreads();
        if (ch + 2 < nch)
            issue_chunk(sb, (ch + 2) % 3, Ab, Bb, m0, n0, twoKb, Kb, (ch + 2) << 5, tid);
        CP_COMMIT();

        uint32_t st = sb + (ch % 3) * STG_SZ;

        #pragma unroll
        for (int ks = 0; ks < 2; ks++) {
            int k0 = ks << 4;
            uint32_t kcA = (k0 >> 3) + (lane >> 4);
            uint32_t ah[4][4], bh[4][2], bl[4][2];

            #pragma unroll
            for (int mt = 0; mt < 4; mt++) {
                uint32_t r = wm0 + mt * 16 + (lane & 15);
                uint32_t addr = st + (r << 6) + ((kcA ^ ((r >> 1) & 3)) << 4);
                LDMX4(ah[mt][0], ah[mt][1], ah[mt][2], ah[mt][3], addr);
            }
            #pragma unroll
            for (int ntp = 0; ntp < 2; ntp++) {
                uint32_t j = lane >> 3;
                uint32_t nt = ntp * 2 + (j >> 1);
                uint32_t kc = (k0 >> 3) + (j & 1);
                uint32_t r = wn0 + nt * 8 + (lane & 7);
                uint32_t soff = (r << 6) + ((kc ^ ((r >> 1) & 3)) << 4);
                uint32_t q0, q1, q2, q3;
                LDMX4(q0, q1, q2, q3, st + 16384 + soff);
                bh[ntp*2][0] = q0;   bh[ntp*2][1] = q1;
                bh[ntp*2+1][0] = q2; bh[ntp*2+1][1] = q3;
                LDMX4(q0, q1, q2, q3, st + 24576 + soff);
                bl[ntp*2][0] = q0;   bl[ntp*2][1] = q1;
                bl[ntp*2+1][0] = q2; bl[ntp*2+1][1] = q3;
            }
            // phase 0: Ah*Bh, phase 1: Ah*Bl
            #pragma unroll
            for (int mt = 0; mt < 4; mt++)
                #pragma unroll
                for (int nt = 0; nt < 4; nt++) {
                    MMA16816(acc[mt][nt], ah[mt], bh[nt]);
                    MMA16816(acc[mt][nt], ah[mt], bl[nt]);
                }
            // phase 2: Al*Bh (reload A frags from Al subtile)
            #pragma unroll
            for (int mt = 0; mt < 4; mt++) {
                uint32_t r = wm0 + mt * 16 + (lane & 15);
                uint32_t addr = st + 8192 + (r << 6) + ((kcA ^ ((r >> 1) & 3)) << 4);
                LDMX4(ah[mt][0], ah[mt][1], ah[mt][2], ah[mt][3], addr);
            }
            #pragma unroll
            for (int mt = 0; mt < 4; mt++)
                #pragma unroll
                for (int nt = 0; nt < 4; nt++)
                    MMA16816(acc[mt][nt], ah[mt], bh[nt]);
        }
    }

    // epilogue from register fragments
    int mrow = wm0 + (lane >> 2);
    int ncol = wn0 + (lane & 3) * 2;
    #pragma unroll
    for (int mt = 0; mt < 4; mt++) {
        #pragma unroll
        for (int nt = 0; nt < 4; nt++) {
            int m = m0 + mrow + mt * 16;
            int n = n0 + ncol + nt * 8;
            float v0 = acc[mt][nt][0], v1 = acc[mt][nt][1];
            float v2 = acc[mt][nt][2], v3 = acc[mt][nt][3];
            if (bias) {
                float2 bb = *(const float2*)(bias + n);
                v0 += bb.x; v1 += bb.y; v2 += bb.x; v3 += bb.y;
            }
            if (act) {
                v0 = 0.5f*v0*(1.0f+erff(v0*0.70710678118654752f));
                v1 = 0.5f*v1*(1.0f+erff(v1*0.70710678118654752f));
                v2 = 0.5f*v2*(1.0f+erff(v2*0.70710678118654752f));
                v3 = 0.5f*v3*(1.0f+erff(v3*0.70710678118654752f));
                #pragma unroll
                for (int h = 0; h < 2; h++) {
                    float a0 = h ? v2 : v0, a1 = h ? v3 : v1;
                    size_t mm = (size_t)(m + h*8);
                    __nv_bfloat16 h0 = __float2bfloat16(a0);
                    __nv_bfloat16 h1 = __float2bfloat16(a1);
                    __nv_bfloat16 l0 = __float2bfloat16(a0 - __bfloat162float(h0));
                    __nv_bfloat16 l1 = __float2bfloat16(a1 - __bfloat162float(h1));
                    __nv_bfloat162 hp; hp.x = h0; hp.y = h1;
                    __nv_bfloat162 lp; lp.x = l0; lp.y = l1;
                    size_t base = mm * (size_t)(2*Ntot) + n;
                    *(__nv_bfloat162*)(outS + base) = hp;
                    *(__nv_bfloat162*)(outS + base + Ntot) = lp;
                }
            } else {
                if (res) {
                    float2 r0 = *(const float2*)(res + (size_t)m * Ntot + n);
                    float2 r1 = *(const float2*)(res + (size_t)(m+8) * Ntot + n);
                    v0 += r0.x; v1 += r0.y; v2 += r1.x; v3 += r1.y;
                }
                float2 o0; o0.x = v0; o0.y = v1;
                float2 o1; o1.x = v2; o1.y = v3;
                *(float2*)(outF + (size_t)m * Ntot + n) = o0;
                *(float2*)(outF + (size_t)(m+8) * Ntot + n) = o1;
            }
        }
    }
}

// ---------------- all weight splits in one launch: [N,K] fp32 -> [N,2K] [hi|lo] ----------------
__global__ void weight_split_all(
    const float* __restrict__ w0, __nv_bfloat16* __restrict__ o0,
    const float* __restrict__ w1, __nv_bfloat16* __restrict__ o1,
    const float* __restrict__ w2, __nv_bfloat16* __restrict__ o2,
    const float* __restrict__ w3, __nv_bfloat16* __restrict__ o3)
{
    int seg = blockIdx.y;
    const float* w; __nv_bfloat16* o; int cnt, Kk;
    if (seg == 0)      { w = w0; o = o0; cnt = 3*CHN*CHN;  Kk = CHN; }
    else if (seg == 1) { w = w1; o = o1; cnt = CHN*CHN;    Kk = CHN; }
    else if (seg == 2) { w = w2; o = o2; cnt = HIDDEN*CHN; Kk = CHN; }
    else               { w = w3; o = o3; cnt = CHN*HIDDEN; Kk = HIDDEN; }
    int idx = blockIdx.x * 256 + threadIdx.x;
    if (idx >= cnt) return;
    int r = idx / Kk, c = idx % Kk;
    float v = w[idx];
    __nv_bfloat16 hi = __float2bfloat16(v);
    __nv_bfloat16 lo = __float2bfloat16(v - __bfloat162float(hi));
    size_t base = (size_t)r * (2 * Kk) + c;
    o[base] = hi;
    o[base + Kk] = lo;
}

// ---------------- depthwise 3x3 conv + residual (NCHW) ----------------
__global__ void dwconv_res(const float* __restrict__ x, const float* __restrict__ w,
                           const float* __restrict__ bias, float* __restrict__ y)
{
    int bc = blockIdx.x;
    int c  = bc % CHN;
    const float* xp = x + (size_t)bc * NTOK;
    float*       yp = y + (size_t)bc * NTOK;

    __shared__ float s[NTOK];
    __shared__ float wk[9];
    for (int i = threadIdx.x; i < NTOK; i += blockDim.x) s[i] = xp[i];
    if (threadIdx.x < 9) wk[threadIdx.x] = w[c*9 + threadIdx.x];
    __syncthreads();

    float bb = bias[c];
    for (int i = threadIdx.x; i < NTOK; i += blockDim.x) {
        int h = i / WW, q = i % WW;
        float acc = bb;
        #pragma unroll
        for (int dh = -1; dh <= 1; dh++)
            #pragma unroll
            for (int dw = -1; dw <= 1; dw++) {
                int hh = h + dh, ww2 = q + dw;
                if (hh >= 0 && hh < HH && ww2 >= 0 && ww2 < WW)
                    acc += wk[(dh+1)*3 + (dw+1)] * s[hh*WW + ww2];
            }
        yp[i] = s[i] + acc;
    }
}

// ---------------- token-major depthwise 3x3 + residual: (B,N,C) -> (B,N,C) ----------------
__global__ void dwconv_tok(const float* __restrict__ t, const float* __restrict__ w,
                           const float* __restrict__ bias, float* __restrict__ y)
{
    __shared__ float sw[CHN*9];
    int b = blockIdx.y, h = blockIdx.x;
    int c = threadIdx.x;                 // 384 threads
    for (int i = c; i < CHN*9; i += CHN) sw[i] = w[i];
    __syncthreads();

    float wr[9];
    #pragma unroll
    for (int j = 0; j < 9; j++) wr[j] = sw[c*9 + j];
    float bb = bias[c];

    const float* tb = t + (size_t)b * NTOK * CHN;
    float* yb = y + (size_t)b * NTOK * CHN;

    for (int q = 0; q < WW; q++) {
        float acc = bb;
        float center = 0.f;
        #pragma unroll
        for (int dh = -1; dh <= 1; dh++) {
            int hh = h + dh;
            if ((unsigned)hh >= HH) continue;
            #pragma unroll
            for (int dw = -1; dw <= 1; dw++) {
                int ww2 = q + dw;
                if ((unsigned)ww2 >= WW) continue;
                float val = __ldg(tb + (size_t)(hh*WW + ww2) * CHN + c);
                acc += wr[(dh+1)*3 + (dw+1)] * val;
                if (dh == 0 && dw == 0) center = val;
            }
        }
        yb[(size_t)(h*WW + q) * CHN + c] = center + acc;
    }
}

// ---------------- layernorm -> dedup split [hi|lo] ----------------
__device__ __forceinline__ float warp_sum(float s) {
    #pragma unroll
    for (int o = 16; o > 0; o >>= 1) s += __shfl_xor_sync(0xffffffffu, s, o);
    return s;
}

__global__ void layernorm_split(const float* __restrict__ in, const float* __restrict__ g,
                                const float* __restrict__ bt, __nv_bfloat16* __restrict__ out)
{
    int row = blockIdx.x;
    int tid = threadIdx.x;          // 128
    int lane = tid & 31, wid = tid >> 5;
    const float* ip = in + (size_t)row * CHN;

    float v0 = ip[tid], v1 = ip[tid+128], v2 = ip[tid+256];
    __shared__ float sred[8];

    float s = warp_sum(v0 + v1 + v2);
    if (lane == 0) sred[wid] = s;
    __syncthreads();
    float mean = (sred[0]+sred[1]+sred[2]+sred[3]) * (1.0f/CHN);

    float d0 = v0-mean, d1 = v1-mean, d2 = v2-mean;
    float s2 = warp_sum(d0*d0 + d1*d1 + d2*d2);
    if (lane == 0) sred[4+wid] = s2;
    __syncthreads();
    float var = (sred[4]+sred[5]+sred[6]+sred[7]) * (1.0f/CHN);
    float rstd = rsqrtf(var + 1e-5f);

    __nv_bfloat16* op = out + (size_t)row * (2*CHN);
    #pragma unroll
    for (int j = 0; j < 3; j++) {
        int cidx = tid + j*128;
        float d = (j==0) ? d0 : (j==1) ? d1 : d2;
        float val = d*rstd*g[cidx] + bt[cidx];
        __nv_bfloat16 hi = __float2bfloat16(val);
        __nv_bfloat16 lo = __float2bfloat16(val - __bfloat162float(hi));
        op[cidx] = hi;
        op[CHN + cidx] = lo;
    }
}

// ---------------- channel attention ----------------
__global__ void attn_kv_k(const float* __restrict__ qkv, float* __restrict__ attn)
{
    int bh = blockIdx.x;
    int b = bh / HEADS, h = bh % HEADS;
    const float* kb = qkv + (size_t)b * NTOK * (3*CHN) + CHN   + h*HDIM;
    const float* vb = qkv + (size_t)b * NTOK * (3*CHN) + 2*CHN + h*HDIM;

    __shared__ float ks[32][33], vs[32][33];
    int e  = threadIdx.x & 31;
    int dg = threadIdx.x >> 5;
    float acc[4] = {0.f, 0.f, 0.f, 0.f};

    for (int n0 = 0; n0 < NTOK; n0 += 32) {
        #pragma unroll
        for (int r = 0; r < 4; r++) {
            int nl = (threadIdx.x >> 5) + r*8;
            int dl = threadIdx.x & 31;
            int n = n0 + nl;
            ks[nl][dl] = (n < NTOK) ? kb[(size_t)n * (3*CHN) + dl] : 0.f;
            vs[nl][dl] = (n < NTOK) ? vb[(size_t)n * (3*CHN) + dl] : 0.f;
        }
        __syncthreads();
        #pragma unroll 8
        for (int nl = 0; nl < 32; nl++) {
            float vv = vs[nl][e];
            #pragma unroll
            for (int i = 0; i < 4; i++) acc[i] = fmaf(ks[nl][dg + 8*i], vv, acc[i]);
        }
        __syncthreads();
    }
    #pragma unroll
    for (int i = 0; i < 4; i++) {
        int d = dg + 8*i;
        attn[(size_t)bh * (HDIM*HDIM) + d*HDIM + e] = acc[i] * SCALE_K;
    }
}

__global__ void softmax32(float* __restrict__ attn)
{
    int r = blockIdx.x * 4 + (threadIdx.x >> 5);
    int lane = threadIdx.x & 31;
    float* p = attn + (size_t)r * 32;
    float v = p[lane];
    float m = v;
    #pragma unroll
    for (int o = 16; o > 0; o >>= 1) m = fmaxf(m, __shfl_xor_sync(0xffffffffu, m, o));
    float ex = expf(v - m);
    float s = ex;
    #pragma unroll
    for (int o = 16; o > 0; o >>= 1) s += __shfl_xor_sync(0xffffffffu, s, o);
    p[lane] = ex / s;
}

// out dedup split [b,n, 2C]: hi at c, lo at C+c
__global__ void attn_apply_split(const float* __restrict__ qkv, const float* __restrict__ attn,
                                 __nv_bfloat16* __restrict__ out)
{
    int bh = blockIdx.x;
    int b = bh / HEADS, h = bh % HEADS;
    int n0 = blockIdx.y * 64;

    __shared__ float As[32][33];
    __shared__ float qs[8][33];

    #pragma unroll
    for (int r = 0; r < 4; r++) {
        int idx = threadIdx.x + r*256;
        As[idx >> 5][idx & 31] = attn[(size_t)bh * (HDIM*HDIM) + idx];
    }
    const float* qb = qkv + (size_t)b * NTOK * (3*CHN) + h*HDIM;
    int d  = threadIdx.x & 31;
    int nl = threadIdx.x >> 5;
    __syncthreads();

    for (int r = 0; r < 8; r++) {
        int n = n0 + r*8 + nl;
        qs[nl][d] = (n < NTOK) ? qb[(size_t)n * (3*CHN) + d] : 0.f;
        __syncthreads();
        float acc = 0.f;
        #pragma unroll
        for (int e = 0; e < 32; e++) acc = fmaf(qs[nl][e], As[d][e], acc);
        if (n < NTOK) {
            __nv_bfloat16 hi = __float2bfloat16(acc);
            __nv_bfloat16 lo = __float2bfloat16(acc - __bfloat162float(hi));
            size_t base = ((size_t)b * NTOK + n) * (2*CHN) + h*HDIM + d;
            out[base] = hi;
            out[base + CHN] = lo;
        }
        __syncthreads();
    }
}

// ---------------- per-batch transpose (B,R,S) -> (B,S,R) ----------------
__global__ void btranspose(const float* __restrict__ in, float* __restrict__ out, int R, int S)
{
    __shared__ float tile[32][33];
    int b  = blockIdx.z;
    int r0 = blockIdx.y * 32, s0 = blockIdx.x * 32;
    const float* ip = in  + (size_t)b * R * S;
    float*       op = out + (size_t)b * R * S;

    int tx = threadIdx.x, ty = threadIdx.y;
    #pragma unroll
    for (int i = 0; i < 32; i += 8) {
        int rr = r0 + ty + i, ss = s0 + tx;
        if (rr < R && ss < S) tile[ty+i][tx] = ip[(size_t)rr * S + ss];
    }
    __syncthreads();
    #pragma unroll
    for (int i = 0; i < 32; i += 8) {
        int ss = s0 + ty + i, rr = r0 + tx;
        if (ss < S && rr < R) op[(size_t)ss * R + rr] = tile[tx][ty+i];
    }
}

// ---------------- host launcher ----------------
extern "C" void kernel_launch(void* const* d_in, const int* in_sizes, int n_in,
                              void* d_out, int out_size)
{
    const float* x      = (const float*)d_in[0];
    const float* cpe1_w = (const float*)d_in[1];
    const float* cpe1_b = (const float*)d_in[2];
    const float* n1_g   = (const float*)d_in[3];
    const float* n1_b   = (const float*)d_in[4];
    const float* qkv_w  = (const float*)d_in[5];
    const float* proj_w = (const float*)d_in[6];
    const float* proj_b = (const float*)d_in[7];
    const float* cpe2_w = (const float*)d_in[8];
    const float* cpe2_b = (const float*)d_in[9];
    const float* n2_g   = (const float*)d_in[10];
    const float* n2_b   = (const float*)d_in[11];
    const float* fc1_w  = (const float*)d_in[12];
    const float* fc1_b  = (const float*)d_in[13];
    const float* fc2_w  = (const float*)d_in[14];
    const float* fc2_b  = (const float*)d_in[15];
    float* out = (float*)d_out;

    float *p_nchwA, *p_xt, *p_qkv, *p_attn, *p_x2, *p_x3, *p_y;
    __nv_bfloat16 *p_curS, *p_aoS, *p_hidS, *p_wqkvS, *p_wprojS, *p_wfc1S, *p_wfc2S;
    cudaGetSymbolAddress((void**)&p_nchwA,  g_nchwA);
    cudaGetSymbolAddress((void**)&p_xt,     g_xt);
    cudaGetSymbolAddress((void**)&p_qkv,    g_qkv);
    cudaGetSymbolAddress((void**)&p_attn,   g_attn);
    cudaGetSymbolAddress((void**)&p_x2,     g_x2);
    cudaGetSymbolAddress((void**)&p_x3,     g_x3);
    cudaGetSymbolAddress((void**)&p_y,      g_y);
    cudaGetSymbolAddress((void**)&p_curS,   g_curS);
    cudaGetSymbolAddress((void**)&p_aoS,    g_aoS);
    cudaGetSymbolAddress((void**)&p_hidS,   g_hidS);
    cudaGetSymbolAddress((void**)&p_wqkvS,  g_wqkvS);
    cudaGetSymbolAddress((void**)&p_wprojS, g_wprojS);
    cudaGetSymbolAddress((void**)&p_wfc1S,  g_wfc1S);
    cudaGetSymbolAddress((void**)&p_wfc2S,  g_wfc2S);

    cudaFuncSetAttribute(gemm_mma, cudaFuncAttributeMaxDynamicSharedMemorySize, GEMM_SMEM);

    dim3 t328(32, 8);

    // weight splits (single launch)
    weight_split_all<<<dim3((HIDDEN*CHN + 255)/256, 4), 256>>>(
        qkv_w, p_wqkvS, proj_w, p_wprojS, fc1_w, p_wfc1S, fc2_w, p_wfc2S);

    // 1) x = x + dwconv1(x)            (NCHW)
    dwconv_res<<<BATCH*CHN, 256>>>(x, cpe1_w, cpe1_b, p_nchwA);
    // 2) transpose -> token-major xt (B,N,C)
    btranspose<<<dim3(25, 12, BATCH), t328>>>(p_nchwA, p_xt, CHN, NTOK);
    // 3) curS = split(LN(xt))
    layernorm_split<<<MROWS, 128>>>(p_xt, n1_g, n1_b, p_curS);
    // 4) qkv = cur @ qkv_w^T
    gemm_mma<<<dim3((3*CHN)/128, MROWS/128), 256, GEMM_SMEM>>>(
        p_curS, p_wqkvS, nullptr, nullptr, p_qkv, nullptr, 3*CHN, CHN, 0);
    // 5-7) channel attention
    attn_kv_k<<<BATCH*HEADS, 256>>>(p_qkv, p_attn);
    softmax32<<<(BATCH*HEADS*HDIM)/4, 128>>>(p_attn);
    attn_apply_split<<<dim3(BATCH*HEADS, 13), 256>>>(p_qkv, p_attn, p_aoS);
    // 8) x2 = xt + ao @ proj_w^T + proj_b   (token-major)
    gemm_mma<<<dim3(CHN/128, MROWS/128), 256, GEMM_SMEM>>>(
        p_aoS, p_wprojS, proj_b, p_xt, p_x2, nullptr, CHN, CHN, 0);
    // 9) x3 = x2 + dwconv2(x2)          (token-major, no transposes)
    dwconv_tok<<<dim3(HH, BATCH), CHN>>>(p_x2, cpe2_w, cpe2_b, p_x3);
    // 10) curS = split(LN(x3))
    layernorm_split<<<MROWS, 128>>>(p_x3, n2_g, n2_b, p_curS);
    // 11) hidS = split(gelu(cur @ fc1^T + b1))
    gemm_mma<<<dim3(HIDDEN/128, MROWS/128), 256, GEMM_SMEM>>>(
        p_curS, p_wfc1S, fc1_b, nullptr, nullptr, p_hidS, HIDDEN, CHN, 1);
    // 12) y = x3 + hid @ fc2^T + b2
    gemm_mma<<<dim3(CHN/128, MROWS/128), 256, GEMM_SMEM>>>(
        p_hidS, p_wfc2S, fc2_b, p_x3, p_y, nullptr, CHN, HIDDEN, 0);
    // 13) final transpose to (B,C,H,W)
    btranspose<<<dim3(12, 25, BATCH), t328>>>(p_y, out, NTOK, CHN);
}

// round 7
// speedup vs baseline: 1.2100x; 1.2100x over previous
#include <cuda_runtime.h>
#include <cuda_fp16.h>
#include <math.h>
#include <stdint.h>

// ---------------- problem constants ----------------
#define BATCH   32
#define CHN     384
#define HH      28
#define WW      28
#define NTOK    784
#define HEADS   12
#define HDIM    32
#define HIDDEN  1536
#define MROWS   (BATCH*NTOK)       // 25088
#define SCALE_K 0.17677669529663687f

// ---------------- scratch ----------------
__device__ float g_nchwA[BATCH*CHN*NTOK];
__device__ float g_xt[MROWS*CHN];
__device__ float g_qkv[(size_t)MROWS*3*CHN];
__device__ float g_attn[BATCH*HEADS*HDIM*HDIM];
__device__ float g_x2[MROWS*CHN];
__device__ float g_x3[MROWS*CHN];
__device__ float g_y[MROWS*CHN];
// plain fp16 activations [rows, K]
__device__ __align__(16) __half g_curH[(size_t)MROWS*CHN];
__device__ __align__(16) __half g_aoH[(size_t)MROWS*CHN];
__device__ __align__(16) __half g_hidH[(size_t)MROWS*HIDDEN];
// split fp16 weights [N, 2K]  layout [hi|lo]
__device__ __align__(16) __half g_wqkvS[(size_t)(3*CHN)*2*CHN];
__device__ __align__(16) __half g_wprojS[(size_t)CHN*2*CHN];
__device__ __align__(16) __half g_wfc1S[(size_t)HIDDEN*2*CHN];
__device__ __align__(16) __half g_wfc2S[(size_t)CHN*2*HIDDEN];

// ---------------- helpers ----------------
__device__ __forceinline__ uint32_t smem_u32(const void* p) {
    uint32_t a;
    asm("{ .reg .u64 t; cvta.to.shared.u64 t, %1; cvt.u32.u64 %0, t; }" : "=r"(a) : "l"(p));
    return a;
}
#define CP16(dst, src) \
    asm volatile("cp.async.cg.shared.global [%0], [%1], 16;" :: "r"(dst), "l"(src))
#define CP_COMMIT() asm volatile("cp.async.commit_group;" ::: "memory")
#define CP_WAIT2()  asm volatile("cp.async.wait_group 2;" ::: "memory")

#define LDMX4(r0,r1,r2,r3,addr) \
    asm volatile("ldmatrix.sync.aligned.m8n8.x4.shared.b16 {%0,%1,%2,%3}, [%4];" \
                 : "=r"(r0), "=r"(r1), "=r"(r2), "=r"(r3) : "r"(addr))

#define MMA16816(d, a, b) \
    asm volatile("mma.sync.aligned.m16n8k16.row.col.f32.f16.f16.f32 " \
        "{%0,%1,%2,%3}, {%4,%5,%6,%7}, {%8,%9}, {%0,%1,%2,%3};" \
        : "+f"((d)[0]), "+f"((d)[1]), "+f"((d)[2]), "+f"((d)[3]) \
        : "r"((a)[0]), "r"((a)[1]), "r"((a)[2]), "r"((a)[3]), "r"((b)[0]), "r"((b)[1]))

// ---------------- mma.sync fp16 GEMM, 2-phase weight split ----------------
// C = A * (Bh + Bl)^T with A plain fp16 [M,K], B split [N,2K] [hi|lo].
// Phase 0: A*Bh (k in [0,K)), phase 1: A*Bl.  A is re-streamed per phase.
// BM=BN=128, BK=32, 4-stage cp.async ring, swizzle c' = c ^ ((row>>1)&3).
#define STG_SZ   16384
#define GEMM_SMEM (4*STG_SZ)

__device__ __forceinline__ void issue_chunk(
    uint32_t sb, int st, const char* Ab, const char* Bb,
    int m0, int n0, int Kb, int aoff, int boff, int tid)
{
    uint32_t sA = sb + st * STG_SZ;
    uint32_t sB = sA + 8192;
    int twoKb = 2 * Kb;
    #pragma unroll
    for (int i = 0; i < 2; i++) {
        int id = tid + (i << 8);
        int r = id >> 2, c = id & 3;
        const char* g = Ab + (((size_t)(m0 + r) * Kb + aoff + (c << 3)) << 1);
        uint32_t d = sA + (r << 6) + ((c ^ ((r >> 1) & 3)) << 4);
        CP16(d, g);
    }
    #pragma unroll
    for (int i = 0; i < 2; i++) {
        int id = tid + (i << 8);
        int r = id >> 2, c = id & 3;
        const char* g = Bb + (((size_t)(n0 + r) * twoKb + boff + (c << 3)) << 1);
        uint32_t d = sB + (r << 6) + ((c ^ ((r >> 1) & 3)) << 4);
        CP16(d, g);
    }
}

__global__ void __launch_bounds__(256, 2) gemm_mma(
    const __half* __restrict__ A, const __half* __restrict__ Bw,
    const float* __restrict__ bias, const float* __restrict__ res,
    float* __restrict__ outF, __half* __restrict__ outS,
    int Ntot, int Kb, int act)
{
    extern __shared__ __align__(128) char smem[];
    uint32_t sb = smem_u32(smem);
    int tid = threadIdx.x, lane = tid & 31, w = tid >> 5;
    int wm0 = (w & 1) * 64;
    int wn0 = (w >> 1) * 32;
    int m0 = blockIdx.y * 128, n0 = blockIdx.x * 128;

    const char* Ab = (const char*)A;
    const char* Bb = (const char*)Bw;
    int nk1 = Kb >> 5;
    int nch = 2 * nk1;

    float acc[4][4][4];
    #pragma unroll
    for (int i = 0; i < 4; i++)
        #pragma unroll
        for (int j = 0; j < 4; j++)
            #pragma unroll
            for (int q = 0; q < 4; q++) acc[i][j][q] = 0.f;

    // chunk ch: phase = ch >= nk1; aoff = base k; boff = base k + phase*Kb
    {
        issue_chunk(sb, 0, Ab, Bb, m0, n0, Kb, 0,  0,  tid); CP_COMMIT();
        int a1 = (1 < nk1) ? 32 : 0, b1 = a1 + ((1 < nk1) ? 0 : Kb);
        issue_chunk(sb, 1, Ab, Bb, m0, n0, Kb, a1, b1, tid); CP_COMMIT();
        int a2 = (2 < nk1) ? 64 : ((2 - nk1) << 5);
        int b2 = a2 + ((2 < nk1) ? 0 : Kb);
        issue_chunk(sb, 2, Ab, Bb, m0, n0, Kb, a2, b2, tid); CP_COMMIT();
    }

    for (int ch = 0; ch < nch; ch++) {
        CP_WAIT2();
        __syncthreads();
        if (ch + 3 < nch) {
            int cn = ch + 3;
            int ph = (cn >= nk1);
            int ao = (cn - (ph ? nk1 : 0)) << 5;
            int bo = ao + (ph ? Kb : 0);
            issue_chunk(sb, (ch + 3) & 3, Ab, Bb, m0, n0, Kb, ao, bo, tid);
        }
        CP_COMMIT();

        uint32_t sA = sb + (ch & 3) * STG_SZ;
        uint32_t sB = sA + 8192;

        #pragma unroll
        for (int ks = 0; ks < 2; ks++) {
            int k0 = ks << 4;
            uint32_t a[4][4], b[4][2];
            #pragma unroll
            for (int mt = 0; mt < 4; mt++) {
                uint32_t r = wm0 + mt * 16 + (lane & 15);
                uint32_t kc = (k0 >> 3) + (lane >> 4);
                uint32_t addr = sA + (r << 6) + ((kc ^ ((r >> 1) & 3)) << 4);
                LDMX4(a[mt][0], a[mt][1], a[mt][2], a[mt][3], addr);
            }
            #pragma unroll
            for (int ntp = 0; ntp < 2; ntp++) {
                uint32_t j = lane >> 3;
                uint32_t nt = ntp * 2 + (j >> 1);
                uint32_t kc = (k0 >> 3) + (j & 1);
                uint32_t r = wn0 + nt * 8 + (lane & 7);
                uint32_t addr = sB + (r << 6) + ((kc ^ ((r >> 1) & 3)) << 4);
                uint32_t q0, q1, q2, q3;
                LDMX4(q0, q1, q2, q3, addr);
                b[ntp*2][0] = q0;   b[ntp*2][1] = q1;
                b[ntp*2+1][0] = q2; b[ntp*2+1][1] = q3;
            }
            #pragma unroll
            for (int mt = 0; mt < 4; mt++)
                #pragma unroll
                for (int nt = 0; nt < 4; nt++)
                    MMA16816(acc[mt][nt], a[mt], b[nt]);
        }
    }

    // epilogue from register fragments
    int mrow = wm0 + (lane >> 2);
    int ncol = wn0 + (lane & 3) * 2;
    #pragma unroll
    for (int mt = 0; mt < 4; mt++) {
        #pragma unroll
        for (int nt = 0; nt < 4; nt++) {
            int m = m0 + mrow + mt * 16;
            int n = n0 + ncol + nt * 8;
            float v0 = acc[mt][nt][0], v1 = acc[mt][nt][1];
            float v2 = acc[mt][nt][2], v3 = acc[mt][nt][3];
            if (bias) {
                float2 bb = *(const float2*)(bias + n);
                v0 += bb.x; v1 += bb.y; v2 += bb.x; v3 += bb.y;
            }
            if (act) {
                v0 = 0.5f*v0*(1.0f+erff(v0*0.70710678118654752f));
                v1 = 0.5f*v1*(1.0f+erff(v1*0.70710678118654752f));
                v2 = 0.5f*v2*(1.0f+erff(v2*0.70710678118654752f));
                v3 = 0.5f*v3*(1.0f+erff(v3*0.70710678118654752f));
                __half2 p0; p0.x = __float2half(v0); p0.y = __float2half(v1);
                __half2 p1; p1.x = __float2half(v2); p1.y = __float2half(v3);
                *(__half2*)(outS + (size_t)m * Ntot + n) = p0;
                *(__half2*)(outS + (size_t)(m+8) * Ntot + n) = p1;
            } else {
                if (res) {
                    float2 r0 = *(const float2*)(res + (size_t)m * Ntot + n);
                    float2 r1 = *(const float2*)(res + (size_t)(m+8) * Ntot + n);
                    v0 += r0.x; v1 += r0.y; v2 += r1.x; v3 += r1.y;
                }
                float2 o0; o0.x = v0; o0.y = v1;
                float2 o1; o1.x = v2; o1.y = v3;
                *(float2*)(outF + (size_t)m * Ntot + n) = o0;
                *(float2*)(outF + (size_t)(m+8) * Ntot + n) = o1;
            }
        }
    }
}

// ---------------- all weight splits in one launch: [N,K] fp32 -> [N,2K] fp16 [hi|lo] ----------------
__global__ void weight_split_all(
    const float* __restrict__ w0, __half* __restrict__ o0,
    const float* __restrict__ w1, __half* __restrict__ o1,
    const float* __restrict__ w2, __half* __restrict__ o2,
    const float* __restrict__ w3, __half* __restrict__ o3)
{
    int seg = blockIdx.y;
    const float* w; __half* o; int cnt, Kk;
    if (seg == 0)      { w = w0; o = o0; cnt = 3*CHN*CHN;  Kk = CHN; }
    else if (seg == 1) { w = w1; o = o1; cnt = CHN*CHN;    Kk = CHN; }
    else if (seg == 2) { w = w2; o = o2; cnt = HIDDEN*CHN; Kk = CHN; }
    else               { w = w3; o = o3; cnt = CHN*HIDDEN; Kk = HIDDEN; }
    int idx = blockIdx.x * 256 + threadIdx.x;
    if (idx >= cnt) return;
    int r = idx / Kk, c = idx % Kk;
    float v = w[idx];
    __half hi = __float2half(v);
    __half lo = __float2half(v - __half2float(hi));
    size_t base = (size_t)r * (2 * Kk) + c;
    o[base] = hi;
    o[base + Kk] = lo;
}

// ---------------- depthwise 3x3 conv + residual (NCHW) ----------------
__global__ void dwconv_res(const float* __restrict__ x, const float* __restrict__ w,
                           const float* __restrict__ bias, float* __restrict__ y)
{
    int bc = blockIdx.x;
    int c  = bc % CHN;
    const float* xp = x + (size_t)bc * NTOK;
    float*       yp = y + (size_t)bc * NTOK;

    __shared__ float s[NTOK];
    __shared__ float wk[9];
    for (int i = threadIdx.x; i < NTOK; i += blockDim.x) s[i] = xp[i];
    if (threadIdx.x < 9) wk[threadIdx.x] = w[c*9 + threadIdx.x];
    __syncthreads();

    float bb = bias[c];
    for (int i = threadIdx.x; i < NTOK; i += blockDim.x) {
        int h = i / WW, q = i % WW;
        float acc = bb;
        #pragma unroll
        for (int dh = -1; dh <= 1; dh++)
            #pragma unroll
            for (int dw = -1; dw <= 1; dw++) {
                int hh = h + dh, ww2 = q + dw;
                if (hh >= 0 && hh < HH && ww2 >= 0 && ww2 < WW)
                    acc += wk[(dh+1)*3 + (dw+1)] * s[hh*WW + ww2];
            }
        yp[i] = s[i] + acc;
    }
}

// ---------------- token-major depthwise 3x3 + residual: (B,N,C) -> (B,N,C) ----------------
__global__ void dwconv_tok(const float* __restrict__ t, const float* __restrict__ w,
                           const float* __restrict__ bias, float* __restrict__ y)
{
    __shared__ float sw[CHN*9];
    int b = blockIdx.y, h = blockIdx.x;
    int c = threadIdx.x;                 // 384 threads
    for (int i = c; i < CHN*9; i += CHN) sw[i] = w[i];
    __syncthreads();

    float wr[9];
    #pragma unroll
    for (int j = 0; j < 9; j++) wr[j] = sw[c*9 + j];
    float bb = bias[c];

    const float* tb = t + (size_t)b * NTOK * CHN;
    float* yb = y + (size_t)b * NTOK * CHN;

    for (int q = 0; q < WW; q++) {
        float acc = bb;
        float center = 0.f;
        #pragma unroll
        for (int dh = -1; dh <= 1; dh++) {
            int hh = h + dh;
            if ((unsigned)hh >= HH) continue;
            #pragma unroll
            for (int dw = -1; dw <= 1; dw++) {
                int ww2 = q + dw;
                if ((unsigned)ww2 >= WW) continue;
                float val = __ldg(tb + (size_t)(hh*WW + ww2) * CHN + c);
                acc += wr[(dh+1)*3 + (dw+1)] * val;
                if (dh == 0 && dw == 0) center = val;
            }
        }
        yb[(size_t)(h*WW + q) * CHN + c] = center + acc;
    }
}

// ---------------- layernorm -> plain fp16 ----------------
__device__ __forceinline__ float warp_sum(float s) {
    #pragma unroll
    for (int o = 16; o > 0; o >>= 1) s += __shfl_xor_sync(0xffffffffu, s, o);
    return s;
}

__global__ void layernorm_h(const float* __restrict__ in, const float* __restrict__ g,
                            const float* __restrict__ bt, __half* __restrict__ out)
{
    int row = blockIdx.x;
    int tid = threadIdx.x;          // 128
    int lane = tid & 31, wid = tid >> 5;
    const float* ip = in + (size_t)row * CHN;

    float v0 = ip[tid], v1 = ip[tid+128], v2 = ip[tid+256];
    __shared__ float sred[8];

    float s = warp_sum(v0 + v1 + v2);
    if (lane == 0) sred[wid] = s;
    __syncthreads();
    float mean = (sred[0]+sred[1]+sred[2]+sred[3]) * (1.0f/CHN);

    float d0 = v0-mean, d1 = v1-mean, d2 = v2-mean;
    float s2 = warp_sum(d0*d0 + d1*d1 + d2*d2);
    if (lane == 0) sred[4+wid] = s2;
    __syncthreads();
    float var = (sred[4]+sred[5]+sred[6]+sred[7]) * (1.0f/CHN);
    float rstd = rsqrtf(var + 1e-5f);

    __half* op = out + (size_t)row * CHN;
    op[tid]     = __float2half(d0*rstd*g[tid]     + bt[tid]);
    op[tid+128] = __float2half(d1*rstd*g[tid+128] + bt[tid+128]);
    op[tid+256] = __float2half(d2*rstd*g[tid+256] + bt[tid+256]);
}

// ---------------- channel attention ----------------
__global__ void attn_kv_k(const float* __restrict__ qkv, float* __restrict__ attn)
{
    int bh = blockIdx.x;
    int b = bh / HEADS, h = bh % HEADS;
    const float* kb = qkv + (size_t)b * NTOK * (3*CHN) + CHN   + h*HDIM;
    const float* vb = qkv + (size_t)b * NTOK * (3*CHN) + 2*CHN + h*HDIM;

    __shared__ float ks[32][33], vs[32][33];
    int e  = threadIdx.x & 31;
    int dg = threadIdx.x >> 5;
    float acc[4] = {0.f, 0.f, 0.f, 0.f};

    for (int n0 = 0; n0 < NTOK; n0 += 32) {
        #pragma unroll
        for (int r = 0; r < 4; r++) {
            int nl = (threadIdx.x >> 5) + r*8;
            int dl = threadIdx.x & 31;
            int n = n0 + nl;
            ks[nl][dl] = (n < NTOK) ? kb[(size_t)n * (3*CHN) + dl] : 0.f;
            vs[nl][dl] = (n < NTOK) ? vb[(size_t)n * (3*CHN) + dl] : 0.f;
        }
        __syncthreads();
        #pragma unroll 8
        for (int nl = 0; nl < 32; nl++) {
            float vv = vs[nl][e];
            #pragma unroll
            for (int i = 0; i < 4; i++) acc[i] = fmaf(ks[nl][dg + 8*i], vv, acc[i]);
        }
        __syncthreads();
    }
    #pragma unroll
    for (int i = 0; i < 4; i++) {
        int d = dg + 8*i;
        attn[(size_t)bh * (HDIM*HDIM) + d*HDIM + e] = acc[i] * SCALE_K;
    }
}

__global__ void softmax32(float* __restrict__ attn)
{
    int r = blockIdx.x * 4 + (threadIdx.x >> 5);
    int lane = threadIdx.x & 31;
    float* p = attn + (size_t)r * 32;
    float v = p[lane];
    float m = v;
    #pragma unroll
    for (int o = 16; o > 0; o >>= 1) m = fmaxf(m, __shfl_xor_sync(0xffffffffu, m, o));
    float ex = expf(v - m);
    float s = ex;
    #pragma unroll
    for (int o = 16; o > 0; o >>= 1) s += __shfl_xor_sync(0xffffffffu, s, o);
    p[lane] = ex / s;
}

// out plain fp16 [b,n,C]
__global__ void attn_apply_h(const float* __restrict__ qkv, const float* __restrict__ attn,
                             __half* __restrict__ out)
{
    int bh = blockIdx.x;
    int b = bh / HEADS, h = bh % HEADS;
    int n0 = blockIdx.y * 64;

    __shared__ float As[32][33];
    __shared__ float qs[8][33];

    #pragma unroll
    for (int r = 0; r < 4; r++) {
        int idx = threadIdx.x + r*256;
        As[idx >> 5][idx & 31] = attn[(size_t)bh * (HDIM*HDIM) + idx];
    }
    const float* qb = qkv + (size_t)b * NTOK * (3*CHN) + h*HDIM;
    int d  = threadIdx.x & 31;
    int nl = threadIdx.x >> 5;
    __syncthreads();

    for (int r = 0; r < 8; r++) {
        int n = n0 + r*8 + nl;
        qs[nl][d] = (n < NTOK) ? qb[(size_t)n * (3*CHN) + d] : 0.f;
        __syncthreads();
        float acc = 0.f;
        #pragma unroll
        for (int e = 0; e < 32; e++) acc = fmaf(qs[nl][e], As[d][e], acc);
        if (n < NTOK)
            out[((size_t)b * NTOK + n) * CHN + h*HDIM + d] = __float2half(acc);
        __syncthreads();
    }
}

// ---------------- per-batch transpose (B,R,S) -> (B,S,R) ----------------
__global__ void btranspose(const float* __restrict__ in, float* __restrict__ out, int R, int S)
{
    __shared__ float tile[32][33];
    int b  = blockIdx.z;
    int r0 = blockIdx.y * 32, s0 = blockIdx.x * 32;
    const float* ip = in  + (size_t)b * R * S;
    float*       op = out + (size_t)b * R * S;

    int tx = threadIdx.x, ty = threadIdx.y;
    #pragma unroll
    for (int i = 0; i < 32; i += 8) {
        int rr = r0 + ty + i, ss = s0 + tx;
        if (rr < R && ss < S) tile[ty+i][tx] = ip[(size_t)rr * S + ss];
    }
    __syncthreads();
    #pragma unroll
    for (int i = 0; i < 32; i += 8) {
        int ss = s0 + ty + i, rr = r0 + tx;
        if (ss < S && rr < R) op[(size_t)ss * R + rr] = tile[tx][ty+i];
    }
}

// ---------------- host launcher ----------------
extern "C" void kernel_launch(void* const* d_in, const int* in_sizes, int n_in,
                              void* d_out, int out_size)
{
    const float* x      = (const float*)d_in[0];
    const float* cpe1_w = (const float*)d_in[1];
    const float* cpe1_b = (const float*)d_in[2];
    const float* n1_g   = (const float*)d_in[3];
    const float* n1_b   = (const float*)d_in[4];
    const float* qkv_w  = (const float*)d_in[5];
    const float* proj_w = (const float*)d_in[6];
    const float* proj_b = (const float*)d_in[7];
    const float* cpe2_w = (const float*)d_in[8];
    const float* cpe2_b = (const float*)d_in[9];
    const float* n2_g   = (const float*)d_in[10];
    const float* n2_b   = (const float*)d_in[11];
    const float* fc1_w  = (const float*)d_in[12];
    const float* fc1_b  = (const float*)d_in[13];
    const float* fc2_w  = (const float*)d_in[14];
    const float* fc2_b  = (const float*)d_in[15];
    float* out = (float*)d_out;

    float *p_nchwA, *p_xt, *p_qkv, *p_attn, *p_x2, *p_x3, *p_y;
    __half *p_curH, *p_aoH, *p_hidH, *p_wqkvS, *p_wprojS, *p_wfc1S, *p_wfc2S;
    cudaGetSymbolAddress((void**)&p_nchwA,  g_nchwA);
    cudaGetSymbolAddress((void**)&p_xt,     g_xt);
    cudaGetSymbolAddress((void**)&p_qkv,    g_qkv);
    cudaGetSymbolAddress((void**)&p_attn,   g_attn);
    cudaGetSymbolAddress((void**)&p_x2,     g_x2);
    cudaGetSymbolAddress((void**)&p_x3,     g_x3);
    cudaGetSymbolAddress((void**)&p_y,      g_y);
    cudaGetSymbolAddress((void**)&p_curH,   g_curH);
    cudaGetSymbolAddress((void**)&p_aoH,    g_aoH);
    cudaGetSymbolAddress((void**)&p_hidH,   g_hidH);
    cudaGetSymbolAddress((void**)&p_wqkvS,  g_wqkvS);
    cudaGetSymbolAddress((void**)&p_wprojS, g_wprojS);
    cudaGetSymbolAddress((void**)&p_wfc1S,  g_wfc1S);
    cudaGetSymbolAddress((void**)&p_wfc2S,  g_wfc2S);

    cudaFuncSetAttribute(gemm_mma, cudaFuncAttributeMaxDynamicSharedMemorySize, GEMM_SMEM);

    dim3 t328(32, 8);

    // weight splits (single launch)
    weight_split_all<<<dim3((HIDDEN*CHN + 255)/256, 4), 256>>>(
        qkv_w, p_wqkvS, proj_w, p_wprojS, fc1_w, p_wfc1S, fc2_w, p_wfc2S);

    // 1) x = x + dwconv1(x)            (NCHW)
    dwconv_res<<<BATCH*CHN, 256>>>(x, cpe1_w, cpe1_b, p_nchwA);
    // 2) transpose -> token-major xt (B,N,C)
    btranspose<<<dim3(25, 12, BATCH), t328>>>(p_nchwA, p_xt, CHN, NTOK);
    // 3) curH = fp16(LN(xt))
    layernorm_h<<<MROWS, 128>>>(p_xt, n1_g, n1_b, p_curH);
    // 4) qkv = cur @ qkv_w^T
    gemm_mma<<<dim3((3*CHN)/128, MROWS/128), 256, GEMM_SMEM>>>(
        p_curH, p_wqkvS, nullptr, nullptr, p_qkv, nullptr, 3*CHN, CHN, 0);
    // 5-7) channel attention
    attn_kv_k<<<BATCH*HEADS, 256>>>(p_qkv, p_attn);
    softmax32<<<(BATCH*HEADS*HDIM)/4, 128>>>(p_attn);
    attn_apply_h<<<dim3(BATCH*HEADS, 13), 256>>>(p_qkv, p_attn, p_aoH);
    // 8) x2 = xt + ao @ proj_w^T + proj_b   (token-major)
    gemm_mma<<<dim3(CHN/128, MROWS/128), 256, GEMM_SMEM>>>(
        p_aoH, p_wprojS, proj_b, p_xt, p_x2, nullptr, CHN, CHN, 0);
    // 9) x3 = x2 + dwconv2(x2)          (token-major, no transposes)
    dwconv_tok<<<dim3(HH, BATCH), CHN>>>(p_x2, cpe2_w, cpe2_b, p_x3);
    // 10) curH = fp16(LN(x3))
    layernorm_h<<<MROWS, 128>>>(p_x3, n2_g, n2_b, p_curH);
    // 11) hidH = fp16(gelu(cur @ fc1^T + b1))
    gemm_mma<<<dim3(HIDDEN/128, MROWS/128), 256, GEMM_SMEM>>>(
        p_curH, p_wfc1S, fc1_b, nullptr, nullptr, p_hidH, HIDDEN, CHN, 1);
    // 12) y = x3 + hid @ fc2^T + b2
    gemm_mma<<<dim3(CHN/128, MROWS/128), 256, GEMM_SMEM>>>(
        p_hidH, p_wfc2S, fc2_b, p_x3, p_y, nullptr, CHN, HIDDEN, 0);
    // 13) final transpose to (B,C,H,W)
    btranspose<<<dim3(12, 25, BATCH), t328>>>(p_y, out, NTOK, CHN);
}

// round 8
// speedup vs baseline: 2.4481x; 2.0232x over previous
#include <cuda_runtime.h>
#include <cuda_fp16.h>
#include <math.h>
#include <stdint.h>

// ---------------- problem constants ----------------
#define BATCH   32
#define CHN     384
#define HH      28
#define WW      28
#define NTOK    784
#define HEADS   12
#define HDIM    32
#define HIDDEN  1536
#define MROWS   (BATCH*NTOK)       // 25088
#define SCALE_K 0.17677669529663687f

// ---------------- scratch ----------------
__device__ float g_nchwA[BATCH*CHN*NTOK];
__device__ float g_xt[MROWS*CHN];
__device__ float g_x2[MROWS*CHN];
__device__ float g_x3[MROWS*CHN];
__device__ float g_y[MROWS*CHN];
__device__ float g_attn[BATCH*HEADS*HDIM*HDIM];
// fp16 activations
__device__ __align__(16) __half g_qkvH[(size_t)MROWS*3*CHN];
__device__ __align__(16) __half g_curH[(size_t)MROWS*CHN];
__device__ __align__(16) __half g_aoH[(size_t)MROWS*CHN];
__device__ __align__(16) __half g_hidH[(size_t)MROWS*HIDDEN];
// fp16 weights [N, K]
__device__ __align__(16) __half g_wqkvH[(size_t)(3*CHN)*CHN];
__device__ __align__(16) __half g_wprojH[(size_t)CHN*CHN];
__device__ __align__(16) __half g_wfc1H[(size_t)HIDDEN*CHN];
__device__ __align__(16) __half g_wfc2H[(size_t)CHN*HIDDEN];

// ---------------- helpers ----------------
__device__ __forceinline__ uint32_t smem_u32(const void* p) {
    uint32_t a;
    asm("{ .reg .u64 t; cvta.to.shared.u64 t, %1; cvt.u32.u64 %0, t; }" : "=r"(a) : "l"(p));
    return a;
}
#define CP16(dst, src) \
    asm volatile("cp.async.cg.shared.global [%0], [%1], 16;" :: "r"(dst), "l"(src))
#define CP_COMMIT() asm volatile("cp.async.commit_group;" ::: "memory")
#define CP_WAIT2()  asm volatile("cp.async.wait_group 2;" ::: "memory")

#define LDMX4(r0,r1,r2,r3,addr) \
    asm volatile("ldmatrix.sync.aligned.m8n8.x4.shared.b16 {%0,%1,%2,%3}, [%4];" \
                 : "=r"(r0), "=r"(r1), "=r"(r2), "=r"(r3) : "r"(addr))

#define MMA16816(d, a, b) \
    asm volatile("mma.sync.aligned.m16n8k16.row.col.f32.f16.f16.f32 " \
        "{%0,%1,%2,%3}, {%4,%5,%6,%7}, {%8,%9}, {%0,%1,%2,%3};" \
        : "+f"((d)[0]), "+f"((d)[1]), "+f"((d)[2]), "+f"((d)[3]) \
        : "r"((a)[0]), "r"((a)[1]), "r"((a)[2]), "r"((a)[3]), "r"((b)[0]), "r"((b)[1]))

// ---------------- plain fp16 mma.sync GEMM ----------------
// C(M,N) = A(M,K) * W(N,K)^T.  BM=BN=128, BK=32, 4-stage cp.async ring,
// swizzle chunk c' = c ^ ((row>>1)&3).
// mode 0: fp32 out (+bias/res);  mode 1: bias+GELU -> fp16 out;  mode 2: plain fp16 out.
#define STG_SZ   16384
#define GEMM_SMEM (4*STG_SZ)

__device__ __forceinline__ void issue_chunk(
    uint32_t sb, int st, const char* Ab, const char* Bb,
    int m0, int n0, int Kb, int kk, int tid)
{
    uint32_t sA = sb + st * STG_SZ;
    uint32_t sB = sA + 8192;
    #pragma unroll
    for (int i = 0; i < 2; i++) {
        int id = tid + (i << 8);
        int r = id >> 2, c = id & 3;
        const char* g = Ab + (((size_t)(m0 + r) * Kb + kk + (c << 3)) << 1);
        uint32_t d = sA + (r << 6) + ((c ^ ((r >> 1) & 3)) << 4);
        CP16(d, g);
    }
    #pragma unroll
    for (int i = 0; i < 2; i++) {
        int id = tid + (i << 8);
        int r = id >> 2, c = id & 3;
        const char* g = Bb + (((size_t)(n0 + r) * Kb + kk + (c << 3)) << 1);
        uint32_t d = sB + (r << 6) + ((c ^ ((r >> 1) & 3)) << 4);
        CP16(d, g);
    }
}

__global__ void __launch_bounds__(256, 2) gemm_mma(
    const __half* __restrict__ A, const __half* __restrict__ Bw,
    const float* __restrict__ bias, const float* __restrict__ res,
    float* __restrict__ outF, __half* __restrict__ outS,
    int Ntot, int Kb, int mode)
{
    extern __shared__ __align__(128) char smem[];
    uint32_t sb = smem_u32(smem);
    int tid = threadIdx.x, lane = tid & 31, w = tid >> 5;
    int wm0 = (w & 1) * 64;
    int wn0 = (w >> 1) * 32;
    int m0 = blockIdx.y * 128, n0 = blockIdx.x * 128;

    const char* Ab = (const char*)A;
    const char* Bb = (const char*)Bw;
    int nch = Kb >> 5;

    float acc[4][4][4];
    #pragma unroll
    for (int i = 0; i < 4; i++)
        #pragma unroll
        for (int j = 0; j < 4; j++)
            #pragma unroll
            for (int q = 0; q < 4; q++) acc[i][j][q] = 0.f;

    issue_chunk(sb, 0, Ab, Bb, m0, n0, Kb, 0,  tid); CP_COMMIT();
    issue_chunk(sb, 1, Ab, Bb, m0, n0, Kb, 32, tid); CP_COMMIT();
    issue_chunk(sb, 2, Ab, Bb, m0, n0, Kb, 64, tid); CP_COMMIT();

    for (int ch = 0; ch < nch; ch++) {
        CP_WAIT2();
        __syncthreads();
        if (ch + 3 < nch)
            issue_chunk(sb, (ch + 3) & 3, Ab, Bb, m0, n0, Kb, (ch + 3) << 5, tid);
        CP_COMMIT();

        uint32_t sA = sb + (ch & 3) * STG_SZ;
        uint32_t sB = sA + 8192;

        #pragma unroll
        for (int ks = 0; ks < 2; ks++) {
            int k0 = ks << 4;
            uint32_t a[4][4], b[4][2];
            #pragma unroll
            for (int mt = 0; mt < 4; mt++) {
                uint32_t r = wm0 + mt * 16 + (lane & 15);
                uint32_t kc = (k0 >> 3) + (lane >> 4);
                uint32_t addr = sA + (r << 6) + ((kc ^ ((r >> 1) & 3)) << 4);
                LDMX4(a[mt][0], a[mt][1], a[mt][2], a[mt][3], addr);
            }
            #pragma unroll
            for (int ntp = 0; ntp < 2; ntp++) {
                uint32_t j = lane >> 3;
                uint32_t nt = ntp * 2 + (j >> 1);
                uint32_t kc = (k0 >> 3) + (j & 1);
                uint32_t r = wn0 + nt * 8 + (lane & 7);
                uint32_t addr = sB + (r << 6) + ((kc ^ ((r >> 1) & 3)) << 4);
                uint32_t q0, q1, q2, q3;
                LDMX4(q0, q1, q2, q3, addr);
                b[ntp*2][0] = q0;   b[ntp*2][1] = q1;
                b[ntp*2+1][0] = q2; b[ntp*2+1][1] = q3;
            }
            #pragma unroll
            for (int mt = 0; mt < 4; mt++)
                #pragma unroll
                for (int nt = 0; nt < 4; nt++)
                    MMA16816(acc[mt][nt], a[mt], b[nt]);
        }
    }

    // epilogue
    int mrow = wm0 + (lane >> 2);
    int ncol = wn0 + (lane & 3) * 2;
    #pragma unroll
    for (int mt = 0; mt < 4; mt++) {
        #pragma unroll
        for (int nt = 0; nt < 4; nt++) {
            int m = m0 + mrow + mt * 16;
            int n = n0 + ncol + nt * 8;
            float v0 = acc[mt][nt][0], v1 = acc[mt][nt][1];
            float v2 = acc[mt][nt][2], v3 = acc[mt][nt][3];
            if (bias) {
                float2 bb = *(const float2*)(bias + n);
                v0 += bb.x; v1 += bb.y; v2 += bb.x; v3 += bb.y;
            }
            if (mode == 1) {
                v0 = 0.5f*v0*(1.0f+erff(v0*0.70710678118654752f));
                v1 = 0.5f*v1*(1.0f+erff(v1*0.70710678118654752f));
                v2 = 0.5f*v2*(1.0f+erff(v2*0.70710678118654752f));
                v3 = 0.5f*v3*(1.0f+erff(v3*0.70710678118654752f));
            }
            if (mode != 0) {
                __half2 p0; p0.x = __float2half(v0); p0.y = __float2half(v1);
                __half2 p1; p1.x = __float2half(v2); p1.y = __float2half(v3);
                *(__half2*)(outS + (size_t)m * Ntot + n) = p0;
                *(__half2*)(outS + (size_t)(m+8) * Ntot + n) = p1;
            } else {
                if (res) {
                    float2 r0 = *(const float2*)(res + (size_t)m * Ntot + n);
                    float2 r1 = *(const float2*)(res + (size_t)(m+8) * Ntot + n);
                    v0 += r0.x; v1 += r0.y; v2 += r1.x; v3 += r1.y;
                }
                float2 o0; o0.x = v0; o0.y = v1;
                float2 o1; o1.x = v2; o1.y = v3;
                *(float2*)(outF + (size_t)m * Ntot + n) = o0;
                *(float2*)(outF + (size_t)(m+8) * Ntot + n) = o1;
            }
        }
    }
}

// ---------------- weight convert (all four in one launch): fp32 -> fp16 ----------------
__global__ void weight_conv_all(
    const float* __restrict__ w0, __half* __restrict__ o0,
    const float* __restrict__ w1, __half* __restrict__ o1,
    const float* __restrict__ w2, __half* __restrict__ o2,
    const float* __restrict__ w3, __half* __restrict__ o3)
{
    int seg = blockIdx.y;
    const float* w; __half* o; int cnt;
    if (seg == 0)      { w = w0; o = o0; cnt = 3*CHN*CHN;  }
    else if (seg == 1) { w = w1; o = o1; cnt = CHN*CHN;    }
    else if (seg == 2) { w = w2; o = o2; cnt = HIDDEN*CHN; }
    else               { w = w3; o = o3; cnt = CHN*HIDDEN; }
    int idx = blockIdx.x * 256 + threadIdx.x;
    if (idx < cnt) o[idx] = __float2half(w[idx]);
}

// ---------------- depthwise 3x3 conv + residual (NCHW) ----------------
__global__ void dwconv_res(const float* __restrict__ x, const float* __restrict__ w,
                           const float* __restrict__ bias, float* __restrict__ y)
{
    int bc = blockIdx.x;
    int c  = bc % CHN;
    const float* xp = x + (size_t)bc * NTOK;
    float*       yp = y + (size_t)bc * NTOK;

    __shared__ float s[NTOK];
    __shared__ float wk[9];
    for (int i = threadIdx.x; i < NTOK; i += blockDim.x) s[i] = xp[i];
    if (threadIdx.x < 9) wk[threadIdx.x] = w[c*9 + threadIdx.x];
    __syncthreads();

    float bb = bias[c];
    for (int i = threadIdx.x; i < NTOK; i += blockDim.x) {
        int h = i / WW, q = i % WW;
        float acc = bb;
        #pragma unroll
        for (int dh = -1; dh <= 1; dh++)
            #pragma unroll
            for (int dw = -1; dw <= 1; dw++) {
                int hh = h + dh, ww2 = q + dw;
                if (hh >= 0 && hh < HH && ww2 >= 0 && ww2 < WW)
                    acc += wk[(dh+1)*3 + (dw+1)] * s[hh*WW + ww2];
            }
        yp[i] = s[i] + acc;
    }
}

// ---------------- token-major depthwise 3x3 + residual ----------------
__global__ void dwconv_tok(const float* __restrict__ t, const float* __restrict__ w,
                           const float* __restrict__ bias, float* __restrict__ y)
{
    __shared__ float sw[CHN*9];
    int b = blockIdx.y, h = blockIdx.x;
    int c = threadIdx.x;                 // 384 threads
    for (int i = c; i < CHN*9; i += CHN) sw[i] = w[i];
    __syncthreads();

    float wr[9];
    #pragma unroll
    for (int j = 0; j < 9; j++) wr[j] = sw[c*9 + j];
    float bb = bias[c];

    const float* tb = t + (size_t)b * NTOK * CHN;
    float* yb = y + (size_t)b * NTOK * CHN;

    for (int q = 0; q < WW; q++) {
        float acc = bb;
        float center = 0.f;
        #pragma unroll
        for (int dh = -1; dh <= 1; dh++) {
            int hh = h + dh;
            if ((unsigned)hh >= HH) continue;
            #pragma unroll
            for (int dw = -1; dw <= 1; dw++) {
                int ww2 = q + dw;
                if ((unsigned)ww2 >= WW) continue;
                float val = __ldg(tb + (size_t)(hh*WW + ww2) * CHN + c);
                acc += wr[(dh+1)*3 + (dw+1)] * val;
                if (dh == 0 && dw == 0) center = val;
            }
        }
        yb[(size_t)(h*WW + q) * CHN + c] = center + acc;
    }
}

// ---------------- layernorm -> fp16 ----------------
__device__ __forceinline__ float warp_sum(float s) {
    #pragma unroll
    for (int o = 16; o > 0; o >>= 1) s += __shfl_xor_sync(0xffffffffu, s, o);
    return s;
}

__global__ void layernorm_h(const float* __restrict__ in, const float* __restrict__ g,
                            const float* __restrict__ bt, __half* __restrict__ out)
{
    int row = blockIdx.x;
    int tid = threadIdx.x;          // 128
    int lane = tid & 31, wid = tid >> 5;
    const float* ip = in + (size_t)row * CHN;

    float v0 = ip[tid], v1 = ip[tid+128], v2 = ip[tid+256];
    __shared__ float sred[8];

    float s = warp_sum(v0 + v1 + v2);
    if (lane == 0) sred[wid] = s;
    __syncthreads();
    float mean = (sred[0]+sred[1]+sred[2]+sred[3]) * (1.0f/CHN);

    float d0 = v0-mean, d1 = v1-mean, d2 = v2-mean;
    float s2 = warp_sum(d0*d0 + d1*d1 + d2*d2);
    if (lane == 0) sred[4+wid] = s2;
    __syncthreads();
    float var = (sred[4]+sred[5]+sred[6]+sred[7]) * (1.0f/CHN);
    float rstd = rsqrtf(var + 1e-5f);

    __half* op = out + (size_t)row * CHN;
    op[tid]     = __float2half(d0*rstd*g[tid]     + bt[tid]);
    op[tid+128] = __float2half(d1*rstd*g[tid+128] + bt[tid+128]);
    op[tid+256] = __float2half(d2*rstd*g[tid+256] + bt[tid+256]);
}

// ---------------- channel attention (fp16 qkv) ----------------
__global__ void attn_kv_k(const __half* __restrict__ qkv, float* __restrict__ attn)
{
    int bh = blockIdx.x;
    int b = bh / HEADS, h = bh % HEADS;
    const __half* kb = qkv + (size_t)b * NTOK * (3*CHN) + CHN   + h*HDIM;
    const __half* vb = qkv + (size_t)b * NTOK * (3*CHN) + 2*CHN + h*HDIM;

    __shared__ float ks[32][33], vs[32][33];
    int e  = threadIdx.x & 31;
    int dg = threadIdx.x >> 5;
    float acc[4] = {0.f, 0.f, 0.f, 0.f};

    for (int n0 = 0; n0 < NTOK; n0 += 32) {
        #pragma unroll
        for (int r = 0; r < 4; r++) {
            int nl = (threadIdx.x >> 5) + r*8;
            int dl = threadIdx.x & 31;
            int n = n0 + nl;
            ks[nl][dl] = (n < NTOK) ? __half2float(kb[(size_t)n * (3*CHN) + dl]) : 0.f;
            vs[nl][dl] = (n < NTOK) ? __half2float(vb[(size_t)n * (3*CHN) + dl]) : 0.f;
        }
        __syncthreads();
        #pragma unroll 8
        for (int nl = 0; nl < 32; nl++) {
            float vv = vs[nl][e];
            #pragma unroll
            for (int i = 0; i < 4; i++) acc[i] = fmaf(ks[nl][dg + 8*i], vv, acc[i]);
        }
        __syncthreads();
    }
    #pragma unroll
    for (int i = 0; i < 4; i++) {
        int d = dg + 8*i;
        attn[(size_t)bh * (HDIM*HDIM) + d*HDIM + e] = acc[i] * SCALE_K;
    }
}

__global__ void softmax32(float* __restrict__ attn)
{
    int r = blockIdx.x * 4 + (threadIdx.x >> 5);
    int lane = threadIdx.x & 31;
    float* p = attn + (size_t)r * 32;
    float v = p[lane];
    float m = v;
    #pragma unroll
    for (int o = 16; o > 0; o >>= 1) m = fmaxf(m, __shfl_xor_sync(0xffffffffu, m, o));
    float ex = expf(v - m);
    float s = ex;
    #pragma unroll
    for (int o = 16; o > 0; o >>= 1) s += __shfl_xor_sync(0xffffffffu, s, o);
    p[lane] = ex / s;
}

// out fp16 [b,n,C]
__global__ void attn_apply_h(const __half* __restrict__ qkv, const float* __restrict__ attn,
                             __half* __restrict__ out)
{
    int bh = blockIdx.x;
    int b = bh / HEADS, h = bh % HEADS;
    int n0 = blockIdx.y * 64;

    __shared__ float As[32][33];
    __shared__ float qs[8][33];

    #pragma unroll
    for (int r = 0; r < 4; r++) {
        int idx = threadIdx.x + r*256;
        As[idx >> 5][idx & 31] = attn[(size_t)bh * (HDIM*HDIM) + idx];
    }
    const __half* qb = qkv + (size_t)b * NTOK * (3*CHN) + h*HDIM;
    int d  = threadIdx.x & 31;
    int nl = threadIdx.x >> 5;
    __syncthreads();

    for (int r = 0; r < 8; r++) {
        int n = n0 + r*8 + nl;
        qs[nl][d] = (n < NTOK) ? __half2float(qb[(size_t)n * (3*CHN) + d]) : 0.f;
        __syncthreads();
        float acc = 0.f;
        #pragma unroll
        for (int e = 0; e < 32; e++) acc = fmaf(qs[nl][e], As[d][e], acc);
        if (n < NTOK)
            out[((size_t)b * NTOK + n) * CHN + h*HDIM + d] = __float2half(acc);
        __syncthreads();
    }
}

// ---------------- per-batch transpose (B,R,S) -> (B,S,R) ----------------
__global__ void btranspose(const float* __restrict__ in, float* __restrict__ out, int R, int S)
{
    __shared__ float tile[32][33];
    int b  = blockIdx.z;
    int r0 = blockIdx.y * 32, s0 = blockIdx.x * 32;
    const float* ip = in  + (size_t)b * R * S;
    float*       op = out + (size_t)b * R * S;

    int tx = threadIdx.x, ty = threadIdx.y;
    #pragma unroll
    for (int i = 0; i < 32; i += 8) {
        int rr = r0 + ty + i, ss = s0 + tx;
        if (rr < R && ss < S) tile[ty+i][tx] = ip[(size_t)rr * S + ss];
    }
    __syncthreads();
    #pragma unroll
    for (int i = 0; i < 32; i += 8) {
        int ss = s0 + ty + i, rr = r0 + tx;
        if (ss < S && rr < R) op[(size_t)ss * R + rr] = tile[tx][ty+i];
    }
}

// ---------------- host launcher ----------------
extern "C" void kernel_launch(void* const* d_in, const int* in_sizes, int n_in,
                              void* d_out, int out_size)
{
    const float* x      = (const float*)d_in[0];
    const float* cpe1_w = (const float*)d_in[1];
    const float* cpe1_b = (const float*)d_in[2];
    const float* n1_g   = (const float*)d_in[3];
    const float* n1_b   = (const float*)d_in[4];
    const float* qkv_w  = (const float*)d_in[5];
    const float* proj_w = (const float*)d_in[6];
    const float* proj_b = (const float*)d_in[7];
    const float* cpe2_w = (const float*)d_in[8];
    const float* cpe2_b = (const float*)d_in[9];
    const float* n2_g   = (const float*)d_in[10];
    const float* n2_b   = (const float*)d_in[11];
    const float* fc1_w  = (const float*)d_in[12];
    const float* fc1_b  = (const float*)d_in[13];
    const float* fc2_w  = (const float*)d_in[14];
    const float* fc2_b  = (const float*)d_in[15];
    float* out = (float*)d_out;

    float *p_nchwA, *p_xt, *p_attn, *p_x2, *p_x3, *p_y;
    __half *p_qkvH, *p_curH, *p_aoH, *p_hidH, *p_wqkvH, *p_wprojH, *p_wfc1H, *p_wfc2H;
    cudaGetSymbolAddress((void**)&p_nchwA,  g_nchwA);
    cudaGetSymbolAddress((void**)&p_xt,     g_xt);
    cudaGetSymbolAddress((void**)&p_attn,   g_attn);
    cudaGetSymbolAddress((void**)&p_x2,     g_x2);
    cudaGetSymbolAddress((void**)&p_x3,     g_x3);
    cudaGetSymbolAddress((void**)&p_y,      g_y);
    cudaGetSymbolAddress((void**)&p_qkvH,   g_qkvH);
    cudaGetSymbolAddress((void**)&p_curH,   g_curH);
    cudaGetSymbolAddress((void**)&p_aoH,    g_aoH);
    cudaGetSymbolAddress((void**)&p_hidH,   g_hidH);
    cudaGetSymbolAddress((void**)&p_wqkvH,  g_wqkvH);
    cudaGetSymbolAddress((void**)&p_wprojH, g_wprojH);
    cudaGetSymbolAddress((void**)&p_wfc1H,  g_wfc1H);
    cudaGetSymbolAddress((void**)&p_wfc2H,  g_wfc2H);

    cudaFuncSetAttribute(gemm_mma, cudaFuncAttributeMaxDynamicSharedMemorySize, GEMM_SMEM);

    dim3 t328(32, 8);

    // weight converts (single launch)
    weight_conv_all<<<dim3((HIDDEN*CHN + 255)/256, 4), 256>>>(
        qkv_w, p_wqkvH, proj_w, p_wprojH, fc1_w, p_wfc1H, fc2_w, p_wfc2H);

    // 1) x = x + dwconv1(x)            (NCHW)
    dwconv_res<<<BATCH*CHN, 256>>>(x, cpe1_w, cpe1_b, p_nchwA);
    // 2) transpose -> token-major xt (B,N,C)
    btranspose<<<dim3(25, 12, BATCH), t328>>>(p_nchwA, p_xt, CHN, NTOK);
    // 3) curH = fp16(LN(xt))
    layernorm_h<<<MROWS, 128>>>(p_xt, n1_g, n1_b, p_curH);
    // 4) qkvH = cur @ qkv_w^T          (fp16 out, no bias)
    gemm_mma<<<dim3((3*CHN)/128, MROWS/128), 256, GEMM_SMEM>>>(
        p_curH, p_wqkvH, nullptr, nullptr, nullptr, p_qkvH, 3*CHN, CHN, 2);
    // 5-7) channel attention
    attn_kv_k<<<BATCH*HEADS, 256>>>(p_qkvH, p_attn);
    softmax32<<<(BATCH*HEADS*HDIM)/4, 128>>>(p_attn);
    attn_apply_h<<<dim3(BATCH*HEADS, 13), 256>>>(p_qkvH, p_attn, p_aoH);
    // 8) x2 = xt + ao @ proj_w^T + proj_b
    gemm_mma<<<dim3(CHN/128, MROWS/128), 256, GEMM_SMEM>>>(
        p_aoH, p_wprojH, proj_b, p_xt, p_x2, nullptr, CHN, CHN, 0);
    // 9) x3 = x2 + dwconv2(x2)          (token-major)
    dwconv_tok<<<dim3(HH, BATCH), CHN>>>(p_x2, cpe2_w, cpe2_b, p_x3);
    // 10) curH = fp16(LN(x3))
    layernorm_h<<<MROWS, 128>>>(p_x3, n2_g, n2_b, p_curH);
    // 11) hidH = fp16(gelu(cur @ fc1^T + b1))
    gemm_mma<<<dim3(HIDDEN/128, MROWS/128), 256, GEMM_SMEM>>>(
        p_curH, p_wfc1H, fc1_b, nullptr, nullptr, p_hidH, HIDDEN, CHN, 1);
    // 12) y = x3 + hid @ fc2^T + b2
    gemm_mma<<<dim3(CHN/128, MROWS/128), 256, GEMM_SMEM>>>(
        p_hidH, p_wfc2H, fc2_b, p_x3, p_y, nullptr, CHN, HIDDEN, 0);
    // 13) final transpose to (B,C,H,W)
    btranspose<<<dim3(12, 25, BATCH), t328>>>(p_y, out, NTOK, CHN);
}

// round 9
// speedup vs baseline: 2.5420x; 1.0384x over previous
#include <cuda_runtime.h>
#include <cuda_fp16.h>
#include <math.h>
#include <stdint.h>

// ---------------- problem constants ----------------
#define BATCH   32
#define CHN     384
#define HH      28
#define WW      28
#define NTOK    784
#define HEADS   12
#define HDIM    32
#define HIDDEN  1536
#define MROWS   (BATCH*NTOK)       // 25088
#define SCALE_K 0.17677669529663687f

// ---------------- scratch ----------------
__device__ float g_nchwA[BATCH*CHN*NTOK];
__device__ float g_xt[MROWS*CHN];
__device__ float g_x2[MROWS*CHN];
__device__ float g_x3[MROWS*CHN];
__device__ float g_attn[BATCH*HEADS*HDIM*HDIM];
// fp16 activations
__device__ __align__(16) __half g_qkvH[(size_t)MROWS*3*CHN];
__device__ __align__(16) __half g_curH[(size_t)MROWS*CHN];
__device__ __align__(16) __half g_aoH[(size_t)MROWS*CHN];
__device__ __align__(16) __half g_hidH[(size_t)MROWS*HIDDEN];
// fp16 weights [N, K]
__device__ __align__(16) __half g_wqkvH[(size_t)(3*CHN)*CHN];
__device__ __align__(16) __half g_wprojH[(size_t)CHN*CHN];
__device__ __align__(16) __half g_wfc1H[(size_t)HIDDEN*CHN];
__device__ __align__(16) __half g_wfc2H[(size_t)CHN*HIDDEN];

// ---------------- helpers ----------------
__device__ __forceinline__ uint32_t smem_u32(const void* p) {
    uint32_t a;
    asm("{ .reg .u64 t; cvta.to.shared.u64 t, %1; cvt.u32.u64 %0, t; }" : "=r"(a) : "l"(p));
    return a;
}
#define CP16(dst, src) \
    asm volatile("cp.async.cg.shared.global [%0], [%1], 16;" :: "r"(dst), "l"(src))
#define CP_COMMIT() asm volatile("cp.async.commit_group;" ::: "memory")
#define CP_WAIT2()  asm volatile("cp.async.wait_group 2;" ::: "memory")

#define LDMX4(r0,r1,r2,r3,addr) \
    asm volatile("ldmatrix.sync.aligned.m8n8.x4.shared.b16 {%0,%1,%2,%3}, [%4];" \
                 : "=r"(r0), "=r"(r1), "=r"(r2), "=r"(r3) : "r"(addr))

#define MMA16816(d, a, b) \
    asm volatile("mma.sync.aligned.m16n8k16.row.col.f32.f16.f16.f32 " \
        "{%0,%1,%2,%3}, {%4,%5,%6,%7}, {%8,%9}, {%0,%1,%2,%3};" \
        : "+f"((d)[0]), "+f"((d)[1]), "+f"((d)[2]), "+f"((d)[3]) \
        : "r"((a)[0]), "r"((a)[1]), "r"((a)[2]), "r"((a)[3]), "r"((b)[0]), "r"((b)[1]))

__device__ __forceinline__ float warp_sum(float s) {
    #pragma unroll
    for (int o = 16; o > 0; o >>= 1) s += __shfl_xor_sync(0xffffffffu, s, o);
    return s;
}
__device__ __forceinline__ float warp_max(float s) {
    #pragma unroll
    for (int o = 16; o > 0; o >>= 1) s = fmaxf(s, __shfl_xor_sync(0xffffffffu, s, o));
    return s;
}

// ---------------- plain fp16 mma.sync GEMM ----------------
// C(M,N) = A(M,K) * W(N,K)^T.  BM=BN=128, BK=32, 4-stage cp.async ring.
// mode 0: fp32 out (+bias/res)
// mode 1: bias+GELU -> fp16 out
// mode 2: plain fp16 out
// mode 3: bias+res -> fp32 NCHW output (smem-staged transpose), outF is (B,C,H,W)
#define STG_SZ   16384
#define GEMM_SMEM  (4*STG_SZ)
#define GEMM_SMEM3 (128*129*4)   // 66048 > 65536, used for mode-3 launch

__device__ __forceinline__ void issue_chunk(
    uint32_t sb, int st, const char* Ab, const char* Bb,
    int m0, int n0, int Kb, int kk, int tid)
{
    uint32_t sA = sb + st * STG_SZ;
    uint32_t sB = sA + 8192;
    #pragma unroll
    for (int i = 0; i < 2; i++) {
        int id = tid + (i << 8);
        int r = id >> 2, c = id & 3;
        const char* g = Ab + (((size_t)(m0 + r) * Kb + kk + (c << 3)) << 1);
        uint32_t d = sA + (r << 6) + ((c ^ ((r >> 1) & 3)) << 4);
        CP16(d, g);
    }
    #pragma unroll
    for (int i = 0; i < 2; i++) {
        int id = tid + (i << 8);
        int r = id >> 2, c = id & 3;
        const char* g = Bb + (((size_t)(n0 + r) * Kb + kk + (c << 3)) << 1);
        uint32_t d = sB + (r << 6) + ((c ^ ((r >> 1) & 3)) << 4);
        CP16(d, g);
    }
}

__global__ void __launch_bounds__(256, 2) gemm_mma(
    const __half* __restrict__ A, const __half* __restrict__ Bw,
    const float* __restrict__ bias, const float* __restrict__ res,
    float* __restrict__ outF, __half* __restrict__ outS,
    int Ntot, int Kb, int mode)
{
    extern __shared__ __align__(128) char smem[];
    uint32_t sb = smem_u32(smem);
    int tid = threadIdx.x, lane = tid & 31, w = tid >> 5;
    int wm0 = (w & 1) * 64;
    int wn0 = (w >> 1) * 32;
    int m0 = blockIdx.y * 128, n0 = blockIdx.x * 128;

    const char* Ab = (const char*)A;
    const char* Bb = (const char*)Bw;
    int nch = Kb >> 5;

    float acc[4][4][4];
    #pragma unroll
    for (int i = 0; i < 4; i++)
        #pragma unroll
        for (int j = 0; j < 4; j++)
            #pragma unroll
            for (int q = 0; q < 4; q++) acc[i][j][q] = 0.f;

    issue_chunk(sb, 0, Ab, Bb, m0, n0, Kb, 0,  tid); CP_COMMIT();
    issue_chunk(sb, 1, Ab, Bb, m0, n0, Kb, 32, tid); CP_COMMIT();
    issue_chunk(sb, 2, Ab, Bb, m0, n0, Kb, 64, tid); CP_COMMIT();

    for (int ch = 0; ch < nch; ch++) {
        CP_WAIT2();
        __syncthreads();
        if (ch + 3 < nch)
            issue_chunk(sb, (ch + 3) & 3, Ab, Bb, m0, n0, Kb, (ch + 3) << 5, tid);
        CP_COMMIT();

        uint32_t sA = sb + (ch & 3) * STG_SZ;
        uint32_t sB = sA + 8192;

        #pragma unroll
        for (int ks = 0; ks < 2; ks++) {
            int k0 = ks << 4;
            uint32_t a[4][4], b[4][2];
            #pragma unroll
            for (int mt = 0; mt < 4; mt++) {
                uint32_t r = wm0 + mt * 16 + (lane & 15);
                uint32_t kc = (k0 >> 3) + (lane >> 4);
                uint32_t addr = sA + (r << 6) + ((kc ^ ((r >> 1) & 3)) << 4);
                LDMX4(a[mt][0], a[mt][1], a[mt][2], a[mt][3], addr);
            }
            #pragma unroll
            for (int ntp = 0; ntp < 2; ntp++) {
                uint32_t j = lane >> 3;
                uint32_t nt = ntp * 2 + (j >> 1);
                uint32_t kc = (k0 >> 3) + (j & 1);
                uint32_t r = wn0 + nt * 8 + (lane & 7);
                uint32_t addr = sB + (r << 6) + ((kc ^ ((r >> 1) & 3)) << 4);
                uint32_t q0, q1, q2, q3;
                LDMX4(q0, q1, q2, q3, addr);
                b[ntp*2][0] = q0;   b[ntp*2][1] = q1;
                b[ntp*2+1][0] = q2; b[ntp*2+1][1] = q3;
            }
            #pragma unroll
            for (int mt = 0; mt < 4; mt++)
                #pragma unroll
                for (int nt = 0; nt < 4; nt++)
                    MMA16816(acc[mt][nt], a[mt], b[nt]);
        }
    }

    int mrow = wm0 + (lane >> 2);
    int ncol = wn0 + (lane & 3) * 2;

    if (mode == 3) {
        // stage tile (bias+res applied) into smem transposed, then write NCHW coalesced
        __syncthreads();
        float* sf = (float*)smem;
        #pragma unroll
        for (int mt = 0; mt < 4; mt++) {
            #pragma unroll
            for (int nt = 0; nt < 4; nt++) {
                int ml = mrow + mt * 16;
                int nl = ncol + nt * 8;
                int m = m0 + ml, n = n0 + nl;
                float v0 = acc[mt][nt][0], v1 = acc[mt][nt][1];
                float v2 = acc[mt][nt][2], v3 = acc[mt][nt][3];
                float2 bb = *(const float2*)(bias + n);
                float2 r0 = *(const float2*)(res + (size_t)m * Ntot + n);
                float2 r1 = *(const float2*)(res + (size_t)(m+8) * Ntot + n);
                v0 += bb.x + r0.x; v1 += bb.y + r0.y;
                v2 += bb.x + r1.x; v3 += bb.y + r1.y;
                sf[nl * 129 + ml]           = v0;
                sf[(nl + 1) * 129 + ml]     = v1;
                sf[nl * 129 + ml + 8]       = v2;
                sf[(nl + 1) * 129 + ml + 8] = v3;
            }
        }
        __syncthreads();
        // out[b, c, t]: warp w handles channels w, w+8, ...; 32 consecutive tokens per store
        #pragma unroll 1
        for (int ci = 0; ci < 16; ci++) {
            int cl = w + ci * 8;
            int cg = n0 + cl;
            #pragma unroll
            for (int rep = 0; rep < 4; rep++) {
                int tl = rep * 32 + lane;
                int m = m0 + tl;
                int b = m / NTOK;
                int t = m - b * NTOK;
                outF[(size_t)b * (CHN*NTOK) + (size_t)cg * NTOK + t] = sf[cl * 129 + tl];
            }
        }
        return;
    }

    #pragma unroll
    for (int mt = 0; mt < 4; mt++) {
        #pragma unroll
        for (int nt = 0; nt < 4; nt++) {
            int m = m0 + mrow + mt * 16;
            int n = n0 + ncol + nt * 8;
            float v0 = acc[mt][nt][0], v1 = acc[mt][nt][1];
            float v2 = acc[mt][nt][2], v3 = acc[mt][nt][3];
            if (bias) {
                float2 bb = *(const float2*)(bias + n);
                v0 += bb.x; v1 += bb.y; v2 += bb.x; v3 += bb.y;
            }
            if (mode == 1) {
                v0 = 0.5f*v0*(1.0f+erff(v0*0.70710678118654752f));
                v1 = 0.5f*v1*(1.0f+erff(v1*0.70710678118654752f));
                v2 = 0.5f*v2*(1.0f+erff(v2*0.70710678118654752f));
                v3 = 0.5f*v3*(1.0f+erff(v3*0.70710678118654752f));
            }
            if (mode != 0) {
                __half2 p0; p0.x = __float2half(v0); p0.y = __float2half(v1);
                __half2 p1; p1.x = __float2half(v2); p1.y = __float2half(v3);
                *(__half2*)(outS + (size_t)m * Ntot + n) = p0;
                *(__half2*)(outS + (size_t)(m+8) * Ntot + n) = p1;
            } else {
                if (res) {
                    float2 r0 = *(const float2*)(res + (size_t)m * Ntot + n);
                    float2 r1 = *(const float2*)(res + (size_t)(m+8) * Ntot + n);
                    v0 += r0.x; v1 += r0.y; v2 += r1.x; v3 += r1.y;
                }
                float2 o0; o0.x = v0; o0.y = v1;
                float2 o1; o1.x = v2; o1.y = v3;
                *(float2*)(outF + (size_t)m * Ntot + n) = o0;
                *(float2*)(outF + (size_t)(m+8) * Ntot + n) = o1;
            }
        }
    }
}

// ---------------- weight convert (all four in one launch): fp32 -> fp16 ----------------
__global__ void weight_conv_all(
    const float* __restrict__ w0, __half* __restrict__ o0,
    const float* __restrict__ w1, __half* __restrict__ o1,
    const float* __restrict__ w2, __half* __restrict__ o2,
    const float* __restrict__ w3, __half* __restrict__ o3)
{
    int seg = blockIdx.y;
    const float* w; __half* o; int cnt;
    if (seg == 0)      { w = w0; o = o0; cnt = 3*CHN*CHN;  }
    else if (seg == 1) { w = w1; o = o1; cnt = CHN*CHN;    }
    else if (seg == 2) { w = w2; o = o2; cnt = HIDDEN*CHN; }
    else               { w = w3; o = o3; cnt = CHN*HIDDEN; }
    int idx = blockIdx.x * 256 + threadIdx.x;
    if (idx < cnt) o[idx] = __float2half(w[idx]);
}

// ---------------- depthwise 3x3 conv + residual (NCHW) ----------------
__global__ void dwconv_res(const float* __restrict__ x, const float* __restrict__ w,
                           const float* __restrict__ bias, float* __restrict__ y)
{
    int bc = blockIdx.x;
    int c  = bc % CHN;
    const float* xp = x + (size_t)bc * NTOK;
    float*       yp = y + (size_t)bc * NTOK;

    __shared__ float s[NTOK];
    __shared__ float wk[9];
    for (int i = threadIdx.x; i < NTOK; i += blockDim.x) s[i] = xp[i];
    if (threadIdx.x < 9) wk[threadIdx.x] = w[c*9 + threadIdx.x];
    __syncthreads();

    float bb = bias[c];
    for (int i = threadIdx.x; i < NTOK; i += blockDim.x) {
        int h = i / WW, q = i % WW;
        float acc = bb;
        #pragma unroll
        for (int dh = -1; dh <= 1; dh++)
            #pragma unroll
            for (int dw = -1; dw <= 1; dw++) {
                int hh = h + dh, ww2 = q + dw;
                if (hh >= 0 && hh < HH && ww2 >= 0 && ww2 < WW)
                    acc += wk[(dh+1)*3 + (dw+1)] * s[hh*WW + ww2];
            }
        yp[i] = s[i] + acc;
    }
}

// ---------------- fused transpose (NCHW -> token-major) + LayerNorm -> fp16 ----------------
// Writes xt (fp32 token-major, pre-LN) and cur (fp16 LN output).
#define TLN_SMEM (32*385*4)
__global__ void trans_ln(const float* __restrict__ in, const float* __restrict__ g,
                         const float* __restrict__ bt,
                         float* __restrict__ xt, __half* __restrict__ cur)
{
    extern __shared__ float st[];          // [32][385]
    int b = blockIdx.y;
    int tok0 = blockIdx.x * 32;
    int tid = threadIdx.x, tx = tid & 31, tyg = tid >> 5;

    #pragma unroll 1
    for (int cg = 0; cg < 12; cg++) {
        #pragma unroll
        for (int i = 0; i < 4; i++) {
            int c = cg * 32 + tyg + i * 8;
            int tok = tok0 + tx;
            float v = (tok < NTOK) ? in[(size_t)b * (CHN*NTOK) + (size_t)c * NTOK + tok] : 0.f;
            st[tx * 385 + c] = v;
        }
    }
    __syncthreads();

    int lane = tid & 31;
    #pragma unroll 1
    for (int p = 0; p < 4; p++) {
        int tk = tyg + p * 8;
        int tok = tok0 + tk;
        if (tok >= NTOK) continue;
        float vals[12];
        float s = 0.f;
        #pragma unroll
        for (int j = 0; j < 12; j++) { vals[j] = st[tk * 385 + lane + 32*j]; s += vals[j]; }
        s = warp_sum(s);
        float mean = s * (1.0f/CHN);
        float s2 = 0.f;
        #pragma unroll
        for (int j = 0; j < 12; j++) { float d = vals[j] - mean; s2 += d * d; }
        s2 = warp_sum(s2);
        float rstd = rsqrtf(s2 * (1.0f/CHN) + 1e-5f);

        size_t row = ((size_t)b * NTOK + tok) * CHN;
        #pragma unroll
        for (int j = 0; j < 12; j++) {
            int cidx = lane + 32*j;
            float v = vals[j];
            xt[row + cidx] = v;
            cur[row + cidx] = __float2half((v - mean) * rstd * g[cidx] + bt[cidx]);
        }
    }
}

// ---------------- token-major depthwise 3x3 + residual ----------------
__global__ void dwconv_tok(const float* __restrict__ t, const float* __restrict__ w,
                           const float* __restrict__ bias, float* __restrict__ y)
{
    __shared__ float sw[CHN*9];
    int b = blockIdx.y, h = blockIdx.x;
    int c = threadIdx.x;                 // 384 threads
    for (int i = c; i < CHN*9; i += CHN) sw[i] = w[i];
    __syncthreads();

    float wr[9];
    #pragma unroll
    for (int j = 0; j < 9; j++) wr[j] = sw[c*9 + j];
    float bb = bias[c];

    const float* tb = t + (size_t)b * NTOK * CHN;
    float* yb = y + (size_t)b * NTOK * CHN;

    for (int q = 0; q < WW; q++) {
        float acc = bb;
        float center = 0.f;
        #pragma unroll
        for (int dh = -1; dh <= 1; dh++) {
            int hh = h + dh;
            if ((unsigned)hh >= HH) continue;
            #pragma unroll
            for (int dw = -1; dw <= 1; dw++) {
                int ww2 = q + dw;
                if ((unsigned)ww2 >= WW) continue;
                float val = __ldg(tb + (size_t)(hh*WW + ww2) * CHN + c);
                acc += wr[(dh+1)*3 + (dw+1)] * val;
                if (dh == 0 && dw == 0) center = val;
            }
        }
        yb[(size_t)(h*WW + q) * CHN + c] = center + acc;
    }
}

// ---------------- layernorm (token-major in) -> fp16 ----------------
__global__ void layernorm_h(const float* __restrict__ in, const float* __restrict__ g,
                            const float* __restrict__ bt, __half* __restrict__ out)
{
    int row = blockIdx.x;
    int tid = threadIdx.x;          // 128
    int lane = tid & 31, wid = tid >> 5;
    const float* ip = in + (size_t)row * CHN;

    float v0 = ip[tid], v1 = ip[tid+128], v2 = ip[tid+256];
    __shared__ float sred[8];

    float s = warp_sum(v0 + v1 + v2);
    if (lane == 0) sred[wid] = s;
    __syncthreads();
    float mean = (sred[0]+sred[1]+sred[2]+sred[3]) * (1.0f/CHN);

    float d0 = v0-mean, d1 = v1-mean, d2 = v2-mean;
    float s2 = warp_sum(d0*d0 + d1*d1 + d2*d2);
    if (lane == 0) sred[4+wid] = s2;
    __syncthreads();
    float var = (sred[4]+sred[5]+sred[6]+sred[7]) * (1.0f/CHN);
    float rstd = rsqrtf(var + 1e-5f);

    __half* op = out + (size_t)row * CHN;
    op[tid]     = __float2half(d0*rstd*g[tid]     + bt[tid]);
    op[tid+128] = __float2half(d1*rstd*g[tid+128] + bt[tid+128]);
    op[tid+256] = __float2half(d2*rstd*g[tid+256] + bt[tid+256]);
}

// ---------------- channel attention: K^T V + fused softmax ----------------
__global__ void attn_kv_sm(const __half* __restrict__ qkv, float* __restrict__ attn)
{
    int bh = blockIdx.x;
    int b = bh / HEADS, h = bh % HEADS;
    const __half* kb = qkv + (size_t)b * NTOK * (3*CHN) + CHN   + h*HDIM;
    const __half* vb = qkv + (size_t)b * NTOK * (3*CHN) + 2*CHN + h*HDIM;

    __shared__ float ks[32][33], vs[32][33];
    int e  = threadIdx.x & 31;
    int dg = threadIdx.x >> 5;
    float acc[4] = {0.f, 0.f, 0.f, 0.f};

    for (int n0 = 0; n0 < NTOK; n0 += 32) {
        #pragma unroll
        for (int r = 0; r < 4; r++) {
            int nl = (threadIdx.x >> 5) + r*8;
            int dl = threadIdx.x & 31;
            int n = n0 + nl;
            ks[nl][dl] = (n < NTOK) ? __half2float(kb[(size_t)n * (3*CHN) + dl]) : 0.f;
            vs[nl][dl] = (n < NTOK) ? __half2float(vb[(size_t)n * (3*CHN) + dl]) : 0.f;
        }
        __syncthreads();
        #pragma unroll 8
        for (int nl = 0; nl < 32; nl++) {
            float vv = vs[nl][e];
            #pragma unroll
            for (int i = 0; i < 4; i++) acc[i] = fmaf(ks[nl][dg + 8*i], vv, acc[i]);
        }
        __syncthreads();
    }
    // softmax over e: each row d = dg+8i lives entirely across this warp's lanes
    #pragma unroll
    for (int i = 0; i < 4; i++) {
        float v = acc[i] * SCALE_K;
        float mx = warp_max(v);
        float ex = expf(v - mx);
        float s = warp_sum(ex);
        int d = dg + 8*i;
        attn[(size_t)bh * (HDIM*HDIM) + d*HDIM + e] = ex / s;
    }
}

// out fp16 [b,n,C]
__global__ void attn_apply_h(const __half* __restrict__ qkv, const float* __restrict__ attn,
                             __half* __restrict__ out)
{
    int bh = blockIdx.x;
    int b = bh / HEADS, h = bh % HEADS;
    int n0 = blockIdx.y * 64;

    __shared__ float As[32][33];
    __shared__ float qs[8][33];

    #pragma unroll
    for (int r = 0; r < 4; r++) {
        int idx = threadIdx.x + r*256;
        As[idx >> 5][idx & 31] = attn[(size_t)bh * (HDIM*HDIM) + idx];
    }
    const __half* qb = qkv + (size_t)b * NTOK * (3*CHN) + h*HDIM;
    int d  = threadIdx.x & 31;
    int nl = threadIdx.x >> 5;
    __syncthreads();

    for (int r = 0; r < 8; r++) {
        int n = n0 + r*8 + nl;
        qs[nl][d] = (n < NTOK) ? __half2float(qb[(size_t)n * (3*CHN) + d]) : 0.f;
        __syncthreads();
        float acc = 0.f;
        #pragma unroll
        for (int e = 0; e < 32; e++) acc = fmaf(qs[nl][e], As[d][e], acc);
        if (n < NTOK)
            out[((size_t)b * NTOK + n) * CHN + h*HDIM + d] = __float2half(acc);
        __syncthreads();
    }
}

// ---------------- host launcher ----------------
extern "C" void kernel_launch(void* const* d_in, const int* in_sizes, int n_in,
                              void* d_out, int out_size)
{
    const float* x      = (const float*)d_in[0];
    const float* cpe1_w = (const float*)d_in[1];
    const float* cpe1_b = (const float*)d_in[2];
    const float* n1_g   = (const float*)d_in[3];
    const float* n1_b   = (const float*)d_in[4];
    const float* qkv_w  = (const float*)d_in[5];
    const float* proj_w = (const float*)d_in[6];
    const float* proj_b = (const float*)d_in[7];
    const float* cpe2_w = (const float*)d_in[8];
    const float* cpe2_b = (const float*)d_in[9];
    const float* n2_g   = (const float*)d_in[10];
    const float* n2_b   = (const float*)d_in[11];
    const float* fc1_w  = (const float*)d_in[12];
    const float* fc1_b  = (const float*)d_in[13];
    const float* fc2_w  = (const float*)d_in[14];
    const float* fc2_b  = (const float*)d_in[15];
    float* out = (float*)d_out;

    float *p_nchwA, *p_xt, *p_attn, *p_x2, *p_x3;
    __half *p_qkvH, *p_curH, *p_aoH, *p_hidH, *p_wqkvH, *p_wprojH, *p_wfc1H, *p_wfc2H;
    cudaGetSymbolAddress((void**)&p_nchwA,  g_nchwA);
    cudaGetSymbolAddress((void**)&p_xt,     g_xt);
    cudaGetSymbolAddress((void**)&p_attn,   g_attn);
    cudaGetSymbolAddress((void**)&p_x2,     g_x2);
    cudaGetSymbolAddress((void**)&p_x3,     g_x3);
    cudaGetSymbolAddress((void**)&p_qkvH,   g_qkvH);
    cudaGetSymbolAddress((void**)&p_curH,   g_curH);
    cudaGetSymbolAddress((void**)&p_aoH,    g_aoH);
    cudaGetSymbolAddress((void**)&p_hidH,   g_hidH);
    cudaGetSymbolAddress((void**)&p_wqkvH,  g_wqkvH);
    cudaGetSymbolAddress((void**)&p_wprojH, g_wprojH);
    cudaGetSymbolAddress((void**)&p_wfc1H,  g_wfc1H);
    cudaGetSymbolAddress((void**)&p_wfc2H,  g_wfc2H);

    cudaFuncSetAttribute(gemm_mma, cudaFuncAttributeMaxDynamicSharedMemorySize, GEMM_SMEM3);
    cudaFuncSetAttribute(trans_ln, cudaFuncAttributeMaxDynamicSharedMemorySize, TLN_SMEM);

    // weight converts (single launch)
    weight_conv_all<<<dim3((HIDDEN*CHN + 255)/256, 4), 256>>>(
        qkv_w, p_wqkvH, proj_w, p_wprojH, fc1_w, p_wfc1H, fc2_w, p_wfc2H);

    // 1) x = x + dwconv1(x)            (NCHW)
    dwconv_res<<<BATCH*CHN, 256>>>(x, cpe1_w, cpe1_b, p_nchwA);
    // 2) fused transpose + LN1: xt (fp32 token-major) + curH (fp16)
    trans_ln<<<dim3(25, BATCH), 256, TLN_SMEM>>>(p_nchwA, n1_g, n1_b, p_xt, p_curH);
    // 3) qkvH = cur @ qkv_w^T          (fp16 out)
    gemm_mma<<<dim3((3*CHN)/128, MROWS/128), 256, GEMM_SMEM>>>(
        p_curH, p_wqkvH, nullptr, nullptr, nullptr, p_qkvH, 3*CHN, CHN, 2);
    // 4) channel attention: K^T V + softmax fused
    attn_kv_sm<<<BATCH*HEADS, 256>>>(p_qkvH, p_attn);
    attn_apply_h<<<dim3(BATCH*HEADS, 13), 256>>>(p_qkvH, p_attn, p_aoH);
    // 5) x2 = xt + ao @ proj_w^T + proj_b
    gemm_mma<<<dim3(CHN/128, MROWS/128), 256, GEMM_SMEM>>>(
        p_aoH, p_wprojH, proj_b, p_xt, p_x2, nullptr, CHN, CHN, 0);
    // 6) x3 = x2 + dwconv2(x2)          (token-major)
    dwconv_tok<<<dim3(HH, BATCH), CHN>>>(p_x2, cpe2_w, cpe2_b, p_x3);
    // 7) curH = fp16(LN2(x3))
    layernorm_h<<<MROWS, 128>>>(p_x3, n2_g, n2_b, p_curH);
    // 8) hidH = fp16(gelu(cur @ fc1^T + b1))
    gemm_mma<<<dim3(HIDDEN/128, MROWS/128), 256, GEMM_SMEM>>>(
        p_curH, p_wfc1H, fc1_b, nullptr, nullptr, p_hidH, HIDDEN, CHN, 1);
    // 9) out(NCHW) = transpose(x3 + hid @ fc2^T + b2)   -- fused epilogue
    gemm_mma<<<dim3(CHN/128, MROWS/128), 256, GEMM_SMEM3>>>(
        p_hidH, p_wfc2H, fc2_b, p_x3, out, nullptr, CHN, HIDDEN, 3);
}